// round 2
// baseline (speedup 1.0000x reference)
#include <cuda_runtime.h>
#include <cstdint>
#include <cstddef>

// Problem constants
#define TT   2048
#define BB   4
#define EE   512
#define HH   8
#define HD   64
#define BH   32            // B*H
#define SCALE 0.125f       // HD^-0.5

// Scratch (static device allocations; no cudaMalloc allowed).
// __align__(16): these are accessed via float4 throughout.
__device__ __align__(16) float g_q [(size_t)BH * TT * HD];     // [bh][t][d], pre-scaled
__device__ __align__(16) float g_k [(size_t)BH * TT * HD];     // [bh][t][d]
__device__ __align__(16) float g_vt[(size_t)BH * HD * TT];     // [bh][d][t]  (V transposed)
__device__ __align__(16) float g_probs[(size_t)BH * TT * TT];  // [bh][q][k]  512 MB
__device__ __align__(16) float g_mid[(size_t)TT * BB * EE];    // attn pre-projection, [t][b][e]

// ---------------------------------------------------------------------------
// Generic tiled GEMM: C = A * B^T (+bias), A is [M][K] lda=LDA, B is [N][K]
// ldb=LDB, both row-major. BK=16, 256 threads, TMxTN register blocking.
// EPI selects operand sources (device scratch vs external) and store mapping.
//   EPI 0: qkv    A=x, B=in_proj_w, bias=in_proj_b -> scatter to g_q/g_k/g_vt
//   EPI 1: scores A=g_q[z], B=g_k[z]               -> g_probs[z]
//   EPI 2: pv     A=g_probs[z], B=g_vt[z]          -> g_mid ([t][b][e] layout)
//   EPI 3: proj   A=g_mid, B=out_w, bias=out_b     -> C (d_out attn region)
// ---------------------------------------------------------------------------
template<int EPI, int BM, int BN, int TM, int TN, int K, int LDA, int LDB>
__global__ __launch_bounds__(256)
void gemm_k(const float* __restrict__ Aext, const float* __restrict__ Bext,
            const float* __restrict__ bias, float* __restrict__ Cext)
{
    static_assert((BM / TM) * (BN / TN) == 256, "thread count");
    constexpr int BK = 16;

    const int z   = blockIdx.z;
    const int tid = threadIdx.x;
    const int tx  = tid % (BN / TN);
    const int ty  = tid / (BN / TN);
    const int m0  = blockIdx.y * BM;
    const int n0  = blockIdx.x * BN;

    const float* A;
    const float* Bm;
    if constexpr (EPI == 0)      { A = Aext;                               Bm = Bext; }
    else if constexpr (EPI == 1) { A = g_q + (size_t)z * TT * HD;          Bm = g_k + (size_t)z * TT * HD; }
    else if constexpr (EPI == 2) { A = g_probs + (size_t)z * TT * TT;      Bm = g_vt + (size_t)z * HD * TT; }
    else                         { A = g_mid;                              Bm = Bext; }

    __shared__ float As[BK][BM + 4];
    __shared__ float Bs[BK][BN + 4];

    float acc[TM][TN];
#pragma unroll
    for (int i = 0; i < TM; i++)
#pragma unroll
        for (int j = 0; j < TN; j++) acc[i][j] = 0.0f;

    const int lrow = tid >> 2;            // 0..63
    const int lcol = (tid & 3) << 2;      // 0,4,8,12

#pragma unroll 1
    for (int k0 = 0; k0 < K; k0 += BK) {
        // Stage A tile (transposed into As[k][m])
#pragma unroll
        for (int r = lrow; r < BM; r += 64) {
            float4 av = *reinterpret_cast<const float4*>(
                &A[(size_t)(m0 + r) * LDA + k0 + lcol]);
            As[lcol + 0][r] = av.x; As[lcol + 1][r] = av.y;
            As[lcol + 2][r] = av.z; As[lcol + 3][r] = av.w;
        }
        // Stage B tile (transposed into Bs[k][n])
#pragma unroll
        for (int r = lrow; r < BN; r += 64) {
            float4 bv = *reinterpret_cast<const float4*>(
                &Bm[(size_t)(n0 + r) * LDB + k0 + lcol]);
            Bs[lcol + 0][r] = bv.x; Bs[lcol + 1][r] = bv.y;
            Bs[lcol + 2][r] = bv.z; Bs[lcol + 3][r] = bv.w;
        }
        __syncthreads();

#pragma unroll
        for (int kk = 0; kk < BK; kk++) {
            float af[TM], bf[TN];
#pragma unroll
            for (int i = 0; i < TM; i += 4) {
                float4 t = *reinterpret_cast<const float4*>(&As[kk][ty * TM + i]);
                af[i] = t.x; af[i + 1] = t.y; af[i + 2] = t.z; af[i + 3] = t.w;
            }
#pragma unroll
            for (int j = 0; j < TN; j += 4) {
                float4 t = *reinterpret_cast<const float4*>(&Bs[kk][tx * TN + j]);
                bf[j] = t.x; bf[j + 1] = t.y; bf[j + 2] = t.z; bf[j + 3] = t.w;
            }
#pragma unroll
            for (int i = 0; i < TM; i++)
#pragma unroll
                for (int j = 0; j < TN; j++)
                    acc[i][j] += af[i] * bf[j];
        }
        __syncthreads();
    }

    // Epilogue
#pragma unroll
    for (int i = 0; i < TM; i++) {
        const int m = m0 + ty * TM + i;
#pragma unroll
        for (int j = 0; j < TN; j++) {
            const int n = n0 + tx * TN + j;
            float v = acc[i][j];
            if constexpr (EPI == 0) {
                v += bias[n];
                const int t = m >> 2, b = m & 3;
                const int sec = n >> 9, h = (n >> 6) & 7, d = n & 63;
                const int bh = b * HH + h;
                if (sec == 0)
                    g_q[((size_t)bh * TT + t) * HD + d] = v * SCALE;
                else if (sec == 1)
                    g_k[((size_t)bh * TT + t) * HD + d] = v;
                else
                    g_vt[((size_t)bh * HD + d) * TT + t] = v;
            } else if constexpr (EPI == 1) {
                g_probs[(size_t)z * TT * TT + (size_t)m * TT + n] = v;
            } else if constexpr (EPI == 2) {
                const int b = z >> 3, h = z & 7;   // z = b*H + h
                g_mid[((size_t)m * BB + b) * EE + h * HD + n] = v;  // m = t, n = d
            } else {
                Cext[(size_t)m * EE + n] = v + bias[n];
            }
        }
    }
}

// ---------------------------------------------------------------------------
// Softmax + head-average. One block per (b, t). Processes all 8 heads:
// normalizes g_probs rows in place (needed by PV), accumulates avg in regs,
// writes avg_weights row (no atomics).
// ---------------------------------------------------------------------------
__global__ __launch_bounds__(256)
void softmax_avg_kernel(float* __restrict__ avg_out)
{
    const int blk  = blockIdx.x;
    const int b    = blk >> 11;        // /2048
    const int t    = blk & 2047;
    const int tid  = threadIdx.x;
    const int lane = tid & 31;
    const int wid  = tid >> 5;

    __shared__ float sh[8];

    float avg0[4] = {0.f, 0.f, 0.f, 0.f};
    float avg1[4] = {0.f, 0.f, 0.f, 0.f};

    for (int h = 0; h < HH; h++) {
        float* row = g_probs + ((size_t)(b * HH + h) * TT + t) * TT;
        float4 v0 = reinterpret_cast<float4*>(row)[tid];
        float4 v1 = reinterpret_cast<float4*>(row)[tid + 256];

        // --- row max ---
        float mx = fmaxf(fmaxf(fmaxf(v0.x, v0.y), fmaxf(v0.z, v0.w)),
                         fmaxf(fmaxf(v1.x, v1.y), fmaxf(v1.z, v1.w)));
#pragma unroll
        for (int o = 16; o; o >>= 1) mx = fmaxf(mx, __shfl_xor_sync(0xffffffffu, mx, o));
        if (lane == 0) sh[wid] = mx;
        __syncthreads();
        if (wid == 0) {
            float m2 = sh[lane & 7];
#pragma unroll
            for (int o = 4; o; o >>= 1) m2 = fmaxf(m2, __shfl_xor_sync(0xffffffffu, m2, o));
            if (lane == 0) sh[0] = m2;
        }
        __syncthreads();
        mx = sh[0];
        __syncthreads();

        // --- exp + sum ---
        v0.x = __expf(v0.x - mx); v0.y = __expf(v0.y - mx);
        v0.z = __expf(v0.z - mx); v0.w = __expf(v0.w - mx);
        v1.x = __expf(v1.x - mx); v1.y = __expf(v1.y - mx);
        v1.z = __expf(v1.z - mx); v1.w = __expf(v1.w - mx);
        float s = (v0.x + v0.y + v0.z + v0.w) + (v1.x + v1.y + v1.z + v1.w);
#pragma unroll
        for (int o = 16; o; o >>= 1) s += __shfl_xor_sync(0xffffffffu, s, o);
        if (lane == 0) sh[wid] = s;
        __syncthreads();
        if (wid == 0) {
            float s2 = sh[lane & 7];
#pragma unroll
            for (int o = 4; o; o >>= 1) s2 += __shfl_xor_sync(0xffffffffu, s2, o);
            if (lane == 0) sh[0] = s2;
        }
        __syncthreads();
        const float inv = 1.0f / sh[0];
        __syncthreads();

        // --- normalize, write back, accumulate average ---
        v0.x *= inv; v0.y *= inv; v0.z *= inv; v0.w *= inv;
        v1.x *= inv; v1.y *= inv; v1.z *= inv; v1.w *= inv;
        reinterpret_cast<float4*>(row)[tid]       = v0;
        reinterpret_cast<float4*>(row)[tid + 256] = v1;
        avg0[0] += v0.x * 0.125f; avg0[1] += v0.y * 0.125f;
        avg0[2] += v0.z * 0.125f; avg0[3] += v0.w * 0.125f;
        avg1[0] += v1.x * 0.125f; avg1[1] += v1.y * 0.125f;
        avg1[2] += v1.z * 0.125f; avg1[3] += v1.w * 0.125f;
    }

    float* arow = avg_out + ((size_t)b * TT + t) * TT;
    reinterpret_cast<float4*>(arow)[tid]       = make_float4(avg0[0], avg0[1], avg0[2], avg0[3]);
    reinterpret_cast<float4*>(arow)[tid + 256] = make_float4(avg1[0], avg1[1], avg1[2], avg1[3]);
}

// ---------------------------------------------------------------------------
extern "C" void kernel_launch(void* const* d_in, const int* in_sizes, int n_in,
                              void* d_out, int out_size)
{
    const float* x     = (const float*)d_in[0];  // [T,B,E]
    const float* w_in  = (const float*)d_in[1];  // [3E,E]
    const float* b_in  = (const float*)d_in[2];  // [3E]
    const float* w_out = (const float*)d_in[3];  // [E,E]
    const float* b_out = (const float*)d_in[4];  // [E]

    float* out      = (float*)d_out;
    float* attn_out = out;                              // T*B*E = 4194304
    float* avg_out  = out + (size_t)TT * BB * EE;       // B*T*T = 16777216

    // 1) QKV in-projection: [8192,512] x [1536,512]^T
    {
        dim3 grid(3 * EE / 128, (TT * BB) / 128, 1);
        gemm_k<0, 128, 128, 8, 8, EE, EE, EE><<<grid, 256>>>(x, w_in, b_in, nullptr);
    }
    // 2) Scores: per-head [2048,64] x [2048,64]^T
    {
        dim3 grid(TT / 128, TT / 128, BH);
        gemm_k<1, 128, 128, 8, 8, HD, HD, HD><<<grid, 256>>>(nullptr, nullptr, nullptr, nullptr);
    }
    // 3) Softmax + head-average
    softmax_avg_kernel<<<TT * BB, 256>>>(avg_out);
    // 4) PV: per-head [2048,2048] x [64,2048]^T  -> g_mid
    {
        dim3 grid(HD / 64, TT / 128, BH);
        gemm_k<2, 128, 64, 8, 4, TT, TT, TT><<<grid, 256>>>(nullptr, nullptr, nullptr, nullptr);
    }
    // 5) Out projection: [8192,512] x [512,512]^T -> d_out
    {
        dim3 grid(EE / 128, (TT * BB) / 128, 1);
        gemm_k<3, 128, 128, 8, 8, EE, EE, EE><<<grid, 256>>>(nullptr, w_out, b_out, attn_out);
    }
}

// round 3
// speedup vs baseline: 1.9479x; 1.9479x over previous
#include <cuda_runtime.h>
#include <cstdint>
#include <cstddef>

// Problem constants
#define TT   2048
#define BB   4
#define EE   512
#define HH   8
#define HD   64
#define BH   32            // B*H
#define SCALE 0.125f       // HD^-0.5

// Scratch (static device allocations; no cudaMalloc allowed).
__device__ __align__(16) float g_q [(size_t)BH * TT * HD];     // [bh][t][d], pre-scaled
__device__ __align__(16) float g_k [(size_t)BH * TT * HD];     // [bh][t][d]
__device__ __align__(16) float g_vt[(size_t)BH * HD * TT];     // [bh][d][t]  (V transposed)
__device__ __align__(16) float g_probs[(size_t)BH * TT * TT];  // [bh][q][k]  512 MB
__device__ __align__(16) float g_mid[(size_t)TT * BB * EE];    // attn pre-projection, [t][b][e]

__device__ __forceinline__ uint32_t to_tf32(float f) {
    uint32_t r;
    asm("cvt.rna.tf32.f32 %0, %1;" : "=r"(r) : "f"(f));
    return r;
}

// ---------------------------------------------------------------------------
// tf32 tensor-core GEMM: C = A * B^T (+bias). A [M][K] lda=LDA, B [N][K]
// ldb=LDB row-major. 256 threads = 8 warps; warp tile WM x WN built from
// mma.sync.m16n8k8.tf32 fragments; fp32 accumulation; double-buffered smem.
// EPI selects operand sources and store mapping (same as fp32 version).
// ---------------------------------------------------------------------------
template<int EPI, int BM, int BN, int WM, int WN, int K, int LDA, int LDB>
__global__ __launch_bounds__(256)
void mma_gemm(const float* __restrict__ Aext, const float* __restrict__ Bext,
              const float* __restrict__ bias, float* __restrict__ Cext)
{
    constexpr int BK = 16;
    constexpr int WARPS_N = BN / WN;
    constexpr int MT = WM / 16;
    constexpr int NT = WN / 8;
    static_assert((BM / WM) * (BN / WN) == 8, "8 warps");

    const int z    = blockIdx.z;
    const int tid  = threadIdx.x;
    const int lane = tid & 31;
    const int warp = tid >> 5;
    const int wm0  = (warp / WARPS_N) * WM;
    const int wn0  = (warp % WARPS_N) * WN;
    const int m0   = blockIdx.y * BM;
    const int n0   = blockIdx.x * BN;

    const float* A;
    const float* Bm;
    if constexpr (EPI == 0)      { A = Aext;                          Bm = Bext; }
    else if constexpr (EPI == 1) { A = g_q + (size_t)z * TT * HD;     Bm = g_k + (size_t)z * TT * HD; }
    else if constexpr (EPI == 2) { A = g_probs + (size_t)z * TT * TT; Bm = g_vt + (size_t)z * HD * TT; }
    else                         { A = g_mid;                         Bm = Bext; }

    __shared__ uint32_t As[2][BK][BM + 4];
    __shared__ uint32_t Bs[2][BK][BN + 4];

    float acc[MT][NT][4];
#pragma unroll
    for (int i = 0; i < MT; i++)
#pragma unroll
        for (int j = 0; j < NT; j++)
#pragma unroll
            for (int c = 0; c < 4; c++) acc[i][j][c] = 0.0f;

    const int lrow = tid >> 2;            // 0..63
    const int lcol = (tid & 3) << 2;      // 0,4,8,12

    // Prologue: stage tile k0=0 into buffer 0
#pragma unroll
    for (int r = lrow; r < BM; r += 64) {
        float4 v = *reinterpret_cast<const float4*>(&A[(size_t)(m0 + r) * LDA + lcol]);
        As[0][lcol + 0][r] = to_tf32(v.x); As[0][lcol + 1][r] = to_tf32(v.y);
        As[0][lcol + 2][r] = to_tf32(v.z); As[0][lcol + 3][r] = to_tf32(v.w);
    }
#pragma unroll
    for (int r = lrow; r < BN; r += 64) {
        float4 v = *reinterpret_cast<const float4*>(&Bm[(size_t)(n0 + r) * LDB + lcol]);
        Bs[0][lcol + 0][r] = to_tf32(v.x); Bs[0][lcol + 1][r] = to_tf32(v.y);
        Bs[0][lcol + 2][r] = to_tf32(v.z); Bs[0][lcol + 3][r] = to_tf32(v.w);
    }
    __syncthreads();

    int buf = 0;
    const int gid = lane >> 2;   // 0..7
    const int tig = lane & 3;    // 0..3

#pragma unroll 1
    for (int k0 = 0; k0 < K; k0 += BK) {
        const bool has_next = (k0 + BK) < K;
        float4 pa[BM / 64], pb[(BN + 63) / 64];
        if (has_next) {
#pragma unroll
            for (int q = 0; q < BM / 64; q++)
                pa[q] = *reinterpret_cast<const float4*>(
                    &A[(size_t)(m0 + lrow + q * 64) * LDA + k0 + BK + lcol]);
#pragma unroll
            for (int q = 0; q < (BN + 63) / 64; q++)
                if (lrow + q * 64 < BN)
                    pb[q] = *reinterpret_cast<const float4*>(
                        &Bm[(size_t)(n0 + lrow + q * 64) * LDB + k0 + BK + lcol]);
        }

        // Compute current buffer: two k8 steps
#pragma unroll
        for (int ks = 0; ks < BK; ks += 8) {
            uint32_t af[MT][4], bf[NT][2];
#pragma unroll
            for (int i = 0; i < MT; i++) {
                const int row = wm0 + i * 16 + gid;
                af[i][0] = As[buf][ks + tig][row];
                af[i][1] = As[buf][ks + tig][row + 8];
                af[i][2] = As[buf][ks + 4 + tig][row];
                af[i][3] = As[buf][ks + 4 + tig][row + 8];
            }
#pragma unroll
            for (int j = 0; j < NT; j++) {
                const int col = wn0 + j * 8 + gid;
                bf[j][0] = Bs[buf][ks + tig][col];
                bf[j][1] = Bs[buf][ks + 4 + tig][col];
            }
#pragma unroll
            for (int i = 0; i < MT; i++)
#pragma unroll
                for (int j = 0; j < NT; j++) {
                    asm volatile(
                        "mma.sync.aligned.m16n8k8.row.col.f32.tf32.tf32.f32 "
                        "{%0,%1,%2,%3}, {%4,%5,%6,%7}, {%8,%9}, {%0,%1,%2,%3};\n"
                        : "+f"(acc[i][j][0]), "+f"(acc[i][j][1]),
                          "+f"(acc[i][j][2]), "+f"(acc[i][j][3])
                        : "r"(af[i][0]), "r"(af[i][1]), "r"(af[i][2]), "r"(af[i][3]),
                          "r"(bf[j][0]), "r"(bf[j][1]));
                }
        }

        if (has_next) {
            const int nb = buf ^ 1;
#pragma unroll
            for (int q = 0; q < BM / 64; q++) {
                const int r = lrow + q * 64;
                As[nb][lcol + 0][r] = to_tf32(pa[q].x); As[nb][lcol + 1][r] = to_tf32(pa[q].y);
                As[nb][lcol + 2][r] = to_tf32(pa[q].z); As[nb][lcol + 3][r] = to_tf32(pa[q].w);
            }
#pragma unroll
            for (int q = 0; q < (BN + 63) / 64; q++) {
                const int r = lrow + q * 64;
                if (r < BN) {
                    Bs[nb][lcol + 0][r] = to_tf32(pb[q].x); Bs[nb][lcol + 1][r] = to_tf32(pb[q].y);
                    Bs[nb][lcol + 2][r] = to_tf32(pb[q].z); Bs[nb][lcol + 3][r] = to_tf32(pb[q].w);
                }
            }
            __syncthreads();
            buf = nb;
        }
    }

    // Epilogue: scatter accumulator fragments per EPI
#pragma unroll
    for (int i = 0; i < MT; i++) {
        const int rbase = m0 + wm0 + i * 16 + gid;
#pragma unroll
        for (int j = 0; j < NT; j++) {
            const int cbase = n0 + wn0 + j * 8 + tig * 2;
#pragma unroll
            for (int c = 0; c < 4; c++) {
                const int m = rbase + (c >> 1) * 8;
                const int n = cbase + (c & 1);
                float v = acc[i][j][c];
                if constexpr (EPI == 0) {
                    v += bias[n];
                    const int t = m >> 2, b = m & 3;
                    const int sec = n >> 9, h = (n >> 6) & 7, d = n & 63;
                    const int bh = b * HH + h;
                    if (sec == 0)
                        g_q[((size_t)bh * TT + t) * HD + d] = v * SCALE;
                    else if (sec == 1)
                        g_k[((size_t)bh * TT + t) * HD + d] = v;
                    else
                        g_vt[((size_t)bh * HD + d) * TT + t] = v;
                } else if constexpr (EPI == 1) {
                    g_probs[(size_t)z * TT * TT + (size_t)m * TT + n] = v;
                } else if constexpr (EPI == 2) {
                    const int b = z >> 3, h = z & 7;
                    g_mid[((size_t)m * BB + b) * EE + h * HD + n] = v;
                } else {
                    Cext[(size_t)m * EE + n] = v + bias[n];
                }
            }
        }
    }
}

// ---------------------------------------------------------------------------
// Softmax + head-average. One block per (b, t); normalizes g_probs rows in
// place and writes avg_weights directly.
// ---------------------------------------------------------------------------
__global__ __launch_bounds__(256)
void softmax_avg_kernel(float* __restrict__ avg_out)
{
    const int blk  = blockIdx.x;
    const int b    = blk >> 11;
    const int t    = blk & 2047;
    const int tid  = threadIdx.x;
    const int lane = tid & 31;
    const int wid  = tid >> 5;

    __shared__ float sh[8];

    float avg0[4] = {0.f, 0.f, 0.f, 0.f};
    float avg1[4] = {0.f, 0.f, 0.f, 0.f};

    for (int h = 0; h < HH; h++) {
        float* row = g_probs + ((size_t)(b * HH + h) * TT + t) * TT;
        float4 v0 = reinterpret_cast<float4*>(row)[tid];
        float4 v1 = reinterpret_cast<float4*>(row)[tid + 256];

        float mx = fmaxf(fmaxf(fmaxf(v0.x, v0.y), fmaxf(v0.z, v0.w)),
                         fmaxf(fmaxf(v1.x, v1.y), fmaxf(v1.z, v1.w)));
#pragma unroll
        for (int o = 16; o; o >>= 1) mx = fmaxf(mx, __shfl_xor_sync(0xffffffffu, mx, o));
        if (lane == 0) sh[wid] = mx;
        __syncthreads();
        if (wid == 0) {
            float m2 = sh[lane & 7];
#pragma unroll
            for (int o = 4; o; o >>= 1) m2 = fmaxf(m2, __shfl_xor_sync(0xffffffffu, m2, o));
            if (lane == 0) sh[0] = m2;
        }
        __syncthreads();
        mx = sh[0];
        __syncthreads();

        v0.x = __expf(v0.x - mx); v0.y = __expf(v0.y - mx);
        v0.z = __expf(v0.z - mx); v0.w = __expf(v0.w - mx);
        v1.x = __expf(v1.x - mx); v1.y = __expf(v1.y - mx);
        v1.z = __expf(v1.z - mx); v1.w = __expf(v1.w - mx);
        float s = (v0.x + v0.y + v0.z + v0.w) + (v1.x + v1.y + v1.z + v1.w);
#pragma unroll
        for (int o = 16; o; o >>= 1) s += __shfl_xor_sync(0xffffffffu, s, o);
        if (lane == 0) sh[wid] = s;
        __syncthreads();
        if (wid == 0) {
            float s2 = sh[lane & 7];
#pragma unroll
            for (int o = 4; o; o >>= 1) s2 += __shfl_xor_sync(0xffffffffu, s2, o);
            if (lane == 0) sh[0] = s2;
        }
        __syncthreads();
        const float inv = 1.0f / sh[0];
        __syncthreads();

        v0.x *= inv; v0.y *= inv; v0.z *= inv; v0.w *= inv;
        v1.x *= inv; v1.y *= inv; v1.z *= inv; v1.w *= inv;
        reinterpret_cast<float4*>(row)[tid]       = v0;
        reinterpret_cast<float4*>(row)[tid + 256] = v1;
        avg0[0] += v0.x * 0.125f; avg0[1] += v0.y * 0.125f;
        avg0[2] += v0.z * 0.125f; avg0[3] += v0.w * 0.125f;
        avg1[0] += v1.x * 0.125f; avg1[1] += v1.y * 0.125f;
        avg1[2] += v1.z * 0.125f; avg1[3] += v1.w * 0.125f;
    }

    float* arow = avg_out + ((size_t)b * TT + t) * TT;
    reinterpret_cast<float4*>(arow)[tid]       = make_float4(avg0[0], avg0[1], avg0[2], avg0[3]);
    reinterpret_cast<float4*>(arow)[tid + 256] = make_float4(avg1[0], avg1[1], avg1[2], avg1[3]);
}

// ---------------------------------------------------------------------------
extern "C" void kernel_launch(void* const* d_in, const int* in_sizes, int n_in,
                              void* d_out, int out_size)
{
    const float* x     = (const float*)d_in[0];  // [T,B,E]
    const float* w_in  = (const float*)d_in[1];  // [3E,E]
    const float* b_in  = (const float*)d_in[2];  // [3E]
    const float* w_out = (const float*)d_in[3];  // [E,E]
    const float* b_out = (const float*)d_in[4];  // [E]

    float* out      = (float*)d_out;
    float* attn_out = out;                              // T*B*E
    float* avg_out  = out + (size_t)TT * BB * EE;       // B*T*T

    // 1) QKV in-projection: [8192,512] x [1536,512]^T
    {
        dim3 grid(3 * EE / 128, (TT * BB) / 128, 1);
        mma_gemm<0, 128, 128, 64, 32, EE, EE, EE><<<grid, 256>>>(x, w_in, b_in, nullptr);
    }
    // 2) Scores: per-head [2048,64] x [2048,64]^T
    {
        dim3 grid(TT / 128, TT / 128, BH);
        mma_gemm<1, 128, 128, 64, 32, HD, HD, HD><<<grid, 256>>>(nullptr, nullptr, nullptr, nullptr);
    }
    // 3) Softmax + head-average
    softmax_avg_kernel<<<TT * BB, 256>>>(avg_out);
    // 4) PV: per-head [2048,2048] x [64,2048]^T -> g_mid
    {
        dim3 grid(HD / 64, TT / 128, BH);
        mma_gemm<2, 128, 64, 32, 32, TT, TT, TT><<<grid, 256>>>(nullptr, nullptr, nullptr, nullptr);
    }
    // 5) Out projection: [8192,512] x [512,512]^T -> d_out
    {
        dim3 grid(EE / 128, (TT * BB) / 128, 1);
        mma_gemm<3, 128, 128, 64, 32, EE, EE, EE><<<grid, 256>>>(nullptr, w_out, b_out, attn_out);
    }
}

// round 4
// speedup vs baseline: 2.1691x; 1.1135x over previous
#include <cuda_runtime.h>
#include <cstdint>
#include <cstddef>

// Problem constants
#define TT   2048
#define BB   4
#define EE   512
#define HH   8
#define HD   64
#define BH   32            // B*H
#define SCALE 0.125f       // HD^-0.5
#define SPAD 18            // smem row pad (uint32 units), keeps LDS.64 8B-aligned

// Scratch (static device allocations; no cudaMalloc allowed).
__device__ __align__(16) float g_q [(size_t)BH * TT * HD];     // [bh][t][d], pre-scaled
__device__ __align__(16) float g_k [(size_t)BH * TT * HD];     // [bh][t][d]
__device__ __align__(16) float g_vt[(size_t)BH * HD * TT];     // [bh][d][t]  (V transposed)
__device__ __align__(16) float g_probs[(size_t)BH * TT * TT];  // [bh][q][k]  holds exp(S)
__device__ __align__(16) float g_mid[(size_t)TT * BB * EE];    // attn pre-projection, [t][b][e]
__device__ __align__(16) float g_Z[(size_t)BH * TT];           // softmax denominators

__device__ __forceinline__ uint32_t to_tf32(float f) {
    uint32_t r;
    asm("cvt.rna.tf32.f32 %0, %1;" : "=r"(r) : "f"(f));
    return r;
}

// k-permutation within a k8 group: samples (tig, tig+4) land adjacent -> LDS.64
__device__ __forceinline__ int kperm(int k) {
    const int g = k >> 3, kk = k & 7;
    return g * 8 + ((kk & 3) * 2 + (kk >> 2));
}

// ---------------------------------------------------------------------------
// tf32 tensor-core GEMM: C = A * B^T (+bias). A [M][K] lda=LDA, B [N][K]
// ldb=LDB row-major. 256 threads = 8 warps; double-buffered smem staged as
// [m][k-permuted] so mma fragments load via LDS.64.
//   EPI 0: qkv    A=x, B=in_proj_w, bias=in_proj_b -> scatter to g_q/g_k/g_vt
//   EPI 1: scores A=g_q[z], B=g_k[z]               -> g_probs[z] = exp(S)
//   EPI 2: pv     A=g_probs[z] (expS), B=g_vt[z]   -> g_mid, scaled by 1/Z
//   EPI 3: proj   A=g_mid, B=out_w, bias=out_b     -> Cext
// ---------------------------------------------------------------------------
template<int EPI, int BM, int BN, int WM, int WN, int K, int LDA, int LDB>
__global__ __launch_bounds__(256)
void mma_gemm(const float* __restrict__ Aext, const float* __restrict__ Bext,
              const float* __restrict__ bias, float* __restrict__ Cext)
{
    constexpr int BK = 16;
    constexpr int WARPS_N = BN / WN;
    constexpr int MT = WM / 16;
    constexpr int NT = WN / 8;
    static_assert((BM / WM) * (BN / WN) == 8, "8 warps");

    const int z    = blockIdx.z;
    const int tid  = threadIdx.x;
    const int lane = tid & 31;
    const int warp = tid >> 5;
    const int wm0  = (warp / WARPS_N) * WM;
    const int wn0  = (warp % WARPS_N) * WN;
    const int m0   = blockIdx.y * BM;
    const int n0   = blockIdx.x * BN;

    const float* A;
    const float* Bm;
    if constexpr (EPI == 0)      { A = Aext;                          Bm = Bext; }
    else if constexpr (EPI == 1) { A = g_q + (size_t)z * TT * HD;     Bm = g_k + (size_t)z * TT * HD; }
    else if constexpr (EPI == 2) { A = g_probs + (size_t)z * TT * TT; Bm = g_vt + (size_t)z * HD * TT; }
    else                         { A = g_mid;                         Bm = Bext; }

    __shared__ __align__(16) uint32_t As[2][BM][SPAD];
    __shared__ __align__(16) uint32_t Bs[2][BN][SPAD];

    float acc[MT][NT][4];
#pragma unroll
    for (int i = 0; i < MT; i++)
#pragma unroll
        for (int j = 0; j < NT; j++)
#pragma unroll
            for (int c = 0; c < 4; c++) acc[i][j][c] = 0.0f;

    const int lrow = tid >> 2;            // 0..63
    const int lcol = (tid & 3) << 2;      // 0,4,8,12
    const int c0 = kperm(lcol), c1 = kperm(lcol + 1),
              c2 = kperm(lcol + 2), c3 = kperm(lcol + 3);

    const int gid = lane >> 2;   // 0..7
    const int tig = lane & 3;    // 0..3

    // Prologue: stage tile k0=0 into buffer 0
#pragma unroll
    for (int r = lrow; r < BM; r += 64) {
        float4 v = *reinterpret_cast<const float4*>(&A[(size_t)(m0 + r) * LDA + lcol]);
        As[0][r][c0] = to_tf32(v.x); As[0][r][c1] = to_tf32(v.y);
        As[0][r][c2] = to_tf32(v.z); As[0][r][c3] = to_tf32(v.w);
    }
#pragma unroll
    for (int r = lrow; r < BN; r += 64) {
        float4 v = *reinterpret_cast<const float4*>(&Bm[(size_t)(n0 + r) * LDB + lcol]);
        Bs[0][r][c0] = to_tf32(v.x); Bs[0][r][c1] = to_tf32(v.y);
        Bs[0][r][c2] = to_tf32(v.z); Bs[0][r][c3] = to_tf32(v.w);
    }
    __syncthreads();

    int buf = 0;

#pragma unroll 1
    for (int k0 = 0; k0 < K; k0 += BK) {
        const bool has_next = (k0 + BK) < K;
        float4 pa[BM / 64], pb[(BN + 63) / 64];
        if (has_next) {
#pragma unroll
            for (int q = 0; q < BM / 64; q++)
                pa[q] = *reinterpret_cast<const float4*>(
                    &A[(size_t)(m0 + lrow + q * 64) * LDA + k0 + BK + lcol]);
#pragma unroll
            for (int q = 0; q < (BN + 63) / 64; q++)
                if (lrow + q * 64 < BN)
                    pb[q] = *reinterpret_cast<const float4*>(
                        &Bm[(size_t)(n0 + lrow + q * 64) * LDB + k0 + BK + lcol]);
        }

        // Compute current buffer: two k8 groups, LDS.64 fragment loads
#pragma unroll
        for (int g = 0; g < 2; g++) {
            const int kc = g * 8 + 2 * tig;
            uint2 alo[MT], ahi[MT], bfr[NT];
#pragma unroll
            for (int i = 0; i < MT; i++) {
                const int row = wm0 + i * 16 + gid;
                alo[i] = *reinterpret_cast<const uint2*>(&As[buf][row][kc]);
                ahi[i] = *reinterpret_cast<const uint2*>(&As[buf][row + 8][kc]);
            }
#pragma unroll
            for (int j = 0; j < NT; j++)
                bfr[j] = *reinterpret_cast<const uint2*>(&Bs[buf][wn0 + j * 8 + gid][kc]);
#pragma unroll
            for (int i = 0; i < MT; i++)
#pragma unroll
                for (int j = 0; j < NT; j++) {
                    asm volatile(
                        "mma.sync.aligned.m16n8k8.row.col.f32.tf32.tf32.f32 "
                        "{%0,%1,%2,%3}, {%4,%5,%6,%7}, {%8,%9}, {%0,%1,%2,%3};\n"
                        : "+f"(acc[i][j][0]), "+f"(acc[i][j][1]),
                          "+f"(acc[i][j][2]), "+f"(acc[i][j][3])
                        : "r"(alo[i].x), "r"(ahi[i].x), "r"(alo[i].y), "r"(ahi[i].y),
                          "r"(bfr[j].x), "r"(bfr[j].y));
                }
        }

        if (has_next) {
            const int nb = buf ^ 1;
#pragma unroll
            for (int q = 0; q < BM / 64; q++) {
                const int r = lrow + q * 64;
                As[nb][r][c0] = to_tf32(pa[q].x); As[nb][r][c1] = to_tf32(pa[q].y);
                As[nb][r][c2] = to_tf32(pa[q].z); As[nb][r][c3] = to_tf32(pa[q].w);
            }
#pragma unroll
            for (int q = 0; q < (BN + 63) / 64; q++) {
                const int r = lrow + q * 64;
                if (r < BN) {
                    Bs[nb][r][c0] = to_tf32(pb[q].x); Bs[nb][r][c1] = to_tf32(pb[q].y);
                    Bs[nb][r][c2] = to_tf32(pb[q].z); Bs[nb][r][c3] = to_tf32(pb[q].w);
                }
            }
            __syncthreads();
            buf = nb;
        }
    }

    // Epilogue
#pragma unroll
    for (int i = 0; i < MT; i++) {
        const int rbase = m0 + wm0 + i * 16 + gid;
        float rz0 = 1.0f, rz1 = 1.0f;
        if constexpr (EPI == 2) {
            rz0 = 1.0f / g_Z[(size_t)z * TT + rbase];
            rz1 = 1.0f / g_Z[(size_t)z * TT + rbase + 8];
        }
#pragma unroll
        for (int j = 0; j < NT; j++) {
            const int cbase = n0 + wn0 + j * 8 + tig * 2;
#pragma unroll
            for (int c = 0; c < 4; c++) {
                const int m = rbase + (c >> 1) * 8;
                const int n = cbase + (c & 1);
                float v = acc[i][j][c];
                if constexpr (EPI == 0) {
                    v += bias[n];
                    const int t = m >> 2, b = m & 3;
                    const int sec = n >> 9, h = (n >> 6) & 7, d = n & 63;
                    const int bh = b * HH + h;
                    if (sec == 0)
                        g_q[((size_t)bh * TT + t) * HD + d] = v * SCALE;
                    else if (sec == 1)
                        g_k[((size_t)bh * TT + t) * HD + d] = v;
                    else
                        g_vt[((size_t)bh * HD + d) * TT + t] = v;
                } else if constexpr (EPI == 1) {
                    g_probs[(size_t)z * TT * TT + (size_t)m * TT + n] = __expf(v);
                } else if constexpr (EPI == 2) {
                    const int b = z >> 3, h = z & 7;
                    g_mid[((size_t)m * BB + b) * EE + h * HD + n] =
                        v * ((c >> 1) ? rz1 : rz0);
                } else {
                    Cext[(size_t)m * EE + n] = v + bias[n];
                }
            }
        }
    }
}

// ---------------------------------------------------------------------------
// Row-sum + head-average. One block per (b, t). Reads exp(S) rows for all 8
// heads, writes Z[bh][t] and the avg_weights row. No max pass needed (scores
// are bounded; exp is safe and softmax is shift-invariant).
// ---------------------------------------------------------------------------
__global__ __launch_bounds__(256)
void sumavg_kernel(float* __restrict__ avg_out)
{
    const int blk  = blockIdx.x;
    const int b    = blk >> 11;
    const int t    = blk & 2047;
    const int tid  = threadIdx.x;
    const int lane = tid & 31;
    const int wid  = tid >> 5;

    __shared__ float sh[8];

    float avg0[4] = {0.f, 0.f, 0.f, 0.f};
    float avg1[4] = {0.f, 0.f, 0.f, 0.f};

    for (int h = 0; h < HH; h++) {
        const float* row = g_probs + ((size_t)(b * HH + h) * TT + t) * TT;
        float4 v0 = reinterpret_cast<const float4*>(row)[tid];
        float4 v1 = reinterpret_cast<const float4*>(row)[tid + 256];

        float s = (v0.x + v0.y + v0.z + v0.w) + (v1.x + v1.y + v1.z + v1.w);
#pragma unroll
        for (int o = 16; o; o >>= 1) s += __shfl_xor_sync(0xffffffffu, s, o);
        if (lane == 0) sh[wid] = s;
        __syncthreads();
        if (wid == 0) {
            float s2 = sh[lane & 7];
#pragma unroll
            for (int o = 4; o; o >>= 1) s2 += __shfl_xor_sync(0xffffffffu, s2, o);
            if (lane == 0) sh[0] = s2;
        }
        __syncthreads();
        const float total = sh[0];
        if (tid == 0) g_Z[(size_t)(b * HH + h) * TT + t] = total;
        const float inv = 0.125f / total;
        __syncthreads();

        avg0[0] += v0.x * inv; avg0[1] += v0.y * inv;
        avg0[2] += v0.z * inv; avg0[3] += v0.w * inv;
        avg1[0] += v1.x * inv; avg1[1] += v1.y * inv;
        avg1[2] += v1.z * inv; avg1[3] += v1.w * inv;
    }

    float* arow = avg_out + ((size_t)b * TT + t) * TT;
    reinterpret_cast<float4*>(arow)[tid]       = make_float4(avg0[0], avg0[1], avg0[2], avg0[3]);
    reinterpret_cast<float4*>(arow)[tid + 256] = make_float4(avg1[0], avg1[1], avg1[2], avg1[3]);
}

// ---------------------------------------------------------------------------
extern "C" void kernel_launch(void* const* d_in, const int* in_sizes, int n_in,
                              void* d_out, int out_size)
{
    const float* x     = (const float*)d_in[0];  // [T,B,E]
    const float* w_in  = (const float*)d_in[1];  // [3E,E]
    const float* b_in  = (const float*)d_in[2];  // [3E]
    const float* w_out = (const float*)d_in[3];  // [E,E]
    const float* b_out = (const float*)d_in[4];  // [E]

    float* out      = (float*)d_out;
    float* attn_out = out;                              // T*B*E
    float* avg_out  = out + (size_t)TT * BB * EE;       // B*T*T

    // 1) QKV in-projection: [8192,512] x [1536,512]^T
    {
        dim3 grid(3 * EE / 128, (TT * BB) / 128, 1);
        mma_gemm<0, 128, 128, 64, 32, EE, EE, EE><<<grid, 256>>>(x, w_in, b_in, nullptr);
    }
    // 2) Scores -> exp(S): per-head [2048,64] x [2048,64]^T
    {
        dim3 grid(TT / 128, TT / 128, BH);
        mma_gemm<1, 128, 128, 64, 32, HD, HD, HD><<<grid, 256>>>(nullptr, nullptr, nullptr, nullptr);
    }
    // 3) Row sums (Z) + head-average output
    sumavg_kernel<<<TT * BB, 256>>>(avg_out);
    // 4) PV: per-head [2048,2048] x [64,2048]^T -> g_mid (scaled by 1/Z)
    {
        dim3 grid(HD / 64, TT / 128, BH);
        mma_gemm<2, 128, 64, 32, 32, TT, TT, TT><<<grid, 256>>>(nullptr, nullptr, nullptr, nullptr);
    }
    // 5) Out projection: [8192,512] x [512,512]^T -> d_out
    {
        dim3 grid(EE / 128, (TT * BB) / 128, 1);
        mma_gemm<3, 128, 128, 64, 32, EE, EE, EE><<<grid, 256>>>(nullptr, w_out, b_out, attn_out);
    }
}

// round 6
// speedup vs baseline: 2.1983x; 1.0135x over previous
#include <cuda_runtime.h>
#include <cstdint>
#include <cstddef>

// Problem constants
#define TT   2048
#define BB   4
#define EE   512
#define HH   8
#define HD   64
#define BH   32            // B*H
#define SCALE 0.125f       // HD^-0.5
#define SPAD 18            // smem row pad for mma_gemm (validated round 4)

// Scratch (static device allocations; no cudaMalloc allowed).
__device__ __align__(16) float g_q [(size_t)BH * TT * HD];     // [bh][t][d], pre-scaled
__device__ __align__(16) float g_k [(size_t)BH * TT * HD];     // [bh][t][d]
__device__ __align__(16) float g_vt[(size_t)BH * HD * TT];     // [bh][d][t]  (V transposed)
__device__ __align__(16) float g_mid[(size_t)TT * BB * EE];    // attn pre-projection, [t][b][e]
__device__ __align__(16) float g_Z[(size_t)BH * TT];           // softmax denominators

__device__ __forceinline__ uint32_t to_tf32(float f) {
    uint32_t r;
    asm("cvt.rna.tf32.f32 %0, %1;" : "=r"(r) : "f"(f));
    return r;
}

#define MMA_TF32(acc, a0, a1, a2, a3, b0, b1)                              \
    asm volatile(                                                          \
        "mma.sync.aligned.m16n8k8.row.col.f32.tf32.tf32.f32 "              \
        "{%0,%1,%2,%3}, {%4,%5,%6,%7}, {%8,%9}, {%0,%1,%2,%3};\n"          \
        : "+f"((acc)[0]), "+f"((acc)[1]), "+f"((acc)[2]), "+f"((acc)[3])   \
        : "r"(a0), "r"(a1), "r"(a2), "r"(a3), "r"(b0), "r"(b1))

// ===========================================================================
// Fused attention: smem layout constants (words = uint32)
// Row strides chosen so stride/2 mod 16 == 4  ->  fragment LDS.64 is
// bank-conflict-free (bank-pair = 4*gid + tig, distinct per 16-lane phase).
// ===========================================================================
constexpr int QS_W = 72;                       // stride for 64-wide k tiles
constexpr int PS_W = 136;                      // stride for 128-wide k tiles
constexpr int QS_OFF = 0;                      // Q  [128][QS_W]
constexpr int KS_OFF = QS_OFF + 128 * QS_W;    // K  [128][QS_W]
constexpr int VS_OFF = KS_OFF + 128 * QS_W;    // V^T[64][PS_W]
constexpr int PS_OFF = VS_OFF + 64 * PS_W;     // P  [128][PS_W]
constexpr int ZS_OFF = PS_OFF + 128 * PS_W;    // zsm[128] floats
constexpr int FUSED_SMEM = (ZS_OFF + 128) * 4; // 178688 B
constexpr int AVG_SMEM   = (2 * 128 * QS_W) * 4; // 73728 B

// Stage a 128x64 fp32 tile into tf32 smem with the k8-group permutation:
// logical k -> g*8 + ((k&3)*2 + ((k&7)>>2)).  For a float4 at c4 (mult of 4)
// the 4 destinations are (c4&~7)+((c4>>2)&1) + {0,2,4,6}.
__device__ __forceinline__ void stage64(uint32_t* __restrict__ dst,
                                        const float* __restrict__ src,
                                        int tid)
{
#pragma unroll
    for (int rr = 0; rr < 2; rr++) {
        const int row = (tid >> 2) + rr * 64;
        const float* s = src + row * HD;
        uint32_t* d = dst + row * QS_W;
#pragma unroll
        for (int cc = 0; cc < 4; cc++) {
            const int c4 = ((tid & 3) + cc * 4) << 2;
            float4 v = *reinterpret_cast<const float4*>(s + c4);
            uint32_t* p = d + (c4 & ~7) + ((c4 >> 2) & 1);
            p[0] = to_tf32(v.x); p[2] = to_tf32(v.y);
            p[4] = to_tf32(v.z); p[6] = to_tf32(v.w);
        }
    }
}

// Stage V^T tile: 64 rows (d) x 128 cols (t), src row stride TT.
__device__ __forceinline__ void stage_v(uint32_t* __restrict__ dst,
                                        const float* __restrict__ src,
                                        int tid)
{
#pragma unroll
    for (int rr = 0; rr < 2; rr++) {
        const int d = (tid >> 3) + rr * 32;
        const float* s = src + (size_t)d * TT;
        uint32_t* dd = dst + d * PS_W;
#pragma unroll
        for (int cc = 0; cc < 4; cc++) {
            const int c4 = ((tid & 7) + cc * 8) << 2;
            float4 v = *reinterpret_cast<const float4*>(s + c4);
            uint32_t* p = dd + (c4 & ~7) + ((c4 >> 2) & 1);
            p[0] = to_tf32(v.x); p[2] = to_tf32(v.y);
            p[4] = to_tf32(v.z); p[6] = to_tf32(v.w);
        }
    }
}

// 128x128x64 QK^T mma: warp tile 64x32 (2 m-warps x 4 n-warps), MT=4, NT=4.
__device__ __forceinline__ void qk_mma(float acc[4][4][4],
                                       const uint32_t* __restrict__ Qs,
                                       const uint32_t* __restrict__ Ks,
                                       int wmq, int wnq, int gid, int tig)
{
#pragma unroll
    for (int g = 0; g < 8; g++) {
        const int kc = g * 8 + 2 * tig;
        uint2 alo[4], ahi[4], bfr[4];
#pragma unroll
        for (int i = 0; i < 4; i++) {
            const int row = wmq + i * 16 + gid;
            alo[i] = *reinterpret_cast<const uint2*>(Qs + row * QS_W + kc);
            ahi[i] = *reinterpret_cast<const uint2*>(Qs + (row + 8) * QS_W + kc);
        }
#pragma unroll
        for (int j = 0; j < 4; j++)
            bfr[j] = *reinterpret_cast<const uint2*>(Ks + (wnq + j * 8 + gid) * QS_W + kc);
#pragma unroll
        for (int i = 0; i < 4; i++)
#pragma unroll
            for (int j = 0; j < 4; j++)
                MMA_TF32(acc[i][j], alo[i].x, ahi[i].x, alo[i].y, ahi[i].y,
                         bfr[j].x, bfr[j].y);
    }
}

// ===========================================================================
// Fused attention kernel: one block per (bh, q-tile of 128).
// ===========================================================================
__global__ __launch_bounds__(256, 1)
void fused_attn()
{
    extern __shared__ uint32_t sm[];
    uint32_t* Qs = sm + QS_OFF;
    uint32_t* Ks = sm + KS_OFF;
    uint32_t* Vs = sm + VS_OFF;
    uint32_t* Ps = sm + PS_OFF;
    float* zsm = reinterpret_cast<float*>(sm + ZS_OFF);

    const int qt = blockIdx.x, bh = blockIdx.y;
    const int tid = threadIdx.x, lane = tid & 31, warp = tid >> 5;
    const int gid = lane >> 2, tig = lane & 3;
    const int wmq = (warp >> 2) * 64, wnq = (warp & 3) * 32;   // QK phase
    const int wmp = (warp >> 1) * 32, wnp = (warp & 1) * 32;   // PV phase

    if (tid < 128) zsm[tid] = 0.0f;
    stage64(Qs, g_q + ((size_t)bh * TT + qt * 128) * HD, tid);

    float oacc[2][4][4];
    float zacc[4][2];
#pragma unroll
    for (int i = 0; i < 2; i++)
#pragma unroll
        for (int j = 0; j < 4; j++)
#pragma unroll
            for (int c = 0; c < 4; c++) oacc[i][j][c] = 0.0f;
#pragma unroll
    for (int i = 0; i < 4; i++) { zacc[i][0] = 0.0f; zacc[i][1] = 0.0f; }

    const float* Kbase = g_k + (size_t)bh * TT * HD;
    const float* Vbase = g_vt + (size_t)bh * HD * TT;

#pragma unroll 1
    for (int kt = 0; kt < 16; kt++) {
        __syncthreads();   // previous iter's consumers done with Ks/Vs
        stage64(Ks, Kbase + (size_t)kt * 128 * HD, tid);
        stage_v(Vs, Vbase + kt * 128, tid);
        __syncthreads();

        // ---- S = Q K^T for this k-tile ----
        float acc[4][4][4];
#pragma unroll
        for (int i = 0; i < 4; i++)
#pragma unroll
            for (int j = 0; j < 4; j++)
#pragma unroll
                for (int c = 0; c < 4; c++) acc[i][j][c] = 0.0f;
        qk_mma(acc, Qs, Ks, wmq, wnq, gid, tig);

        // ---- exp(S) -> Ps (tf32), accumulate Z partials ----
#pragma unroll
        for (int i = 0; i < 4; i++)
#pragma unroll
            for (int c2 = 0; c2 < 2; c2++) {
                const int row = wmq + i * 16 + gid + c2 * 8;
                uint32_t* prow = Ps + row * PS_W;
                float zp = 0.0f;
#pragma unroll
                for (int j = 0; j < 4; j++)
#pragma unroll
                    for (int c1 = 0; c1 < 2; c1++) {
                        const float e = __expf(acc[i][j][c2 * 2 + c1]);
                        const int kk = 2 * tig + c1;
                        prow[wnq + j * 8 + ((kk & 3) * 2) + (kk >> 2)] = to_tf32(e);
                        zp += e;
                    }
                zacc[i][c2] += zp;
            }
        __syncthreads();   // Ps complete

        // ---- O += P V : M128 x N64 x K128, warp tile 32x32, MT=2, NT=4 ----
#pragma unroll
        for (int g = 0; g < 16; g++) {
            const int kc = g * 8 + 2 * tig;
            uint2 alo[2], ahi[2], bfr[4];
#pragma unroll
            for (int i = 0; i < 2; i++) {
                const int row = wmp + i * 16 + gid;
                alo[i] = *reinterpret_cast<const uint2*>(Ps + row * PS_W + kc);
                ahi[i] = *reinterpret_cast<const uint2*>(Ps + (row + 8) * PS_W + kc);
            }
#pragma unroll
            for (int j = 0; j < 4; j++)
                bfr[j] = *reinterpret_cast<const uint2*>(Vs + (wnp + j * 8 + gid) * PS_W + kc);
#pragma unroll
            for (int i = 0; i < 2; i++)
#pragma unroll
                for (int j = 0; j < 4; j++)
                    MMA_TF32(oacc[i][j], alo[i].x, ahi[i].x, alo[i].y, ahi[i].y,
                             bfr[j].x, bfr[j].y);
        }
    }

    // ---- Z reduction across lanes/warps ----
#pragma unroll
    for (int i = 0; i < 4; i++) {
        atomicAdd(&zsm[wmq + i * 16 + gid],     zacc[i][0]);
        atomicAdd(&zsm[wmq + i * 16 + gid + 8], zacc[i][1]);
    }
    __syncthreads();
    if (tid < 128) g_Z[(size_t)bh * TT + qt * 128 + tid] = zsm[tid];

    // ---- epilogue: O / Z -> g_mid [t][b][e] ----
    const int b = bh >> 3, h = bh & 7;
#pragma unroll
    for (int i = 0; i < 2; i++) {
        const int r0 = wmp + i * 16 + gid;
        const float rz0 = 1.0f / zsm[r0];
        const float rz1 = 1.0f / zsm[r0 + 8];
#pragma unroll
        for (int j = 0; j < 4; j++)
#pragma unroll
            for (int c2 = 0; c2 < 2; c2++) {
                const int rowl = r0 + c2 * 8;
                const int d = wnp + j * 8 + 2 * tig;
                const int t = qt * 128 + rowl;
                const float rz = c2 ? rz1 : rz0;
                float2 v = make_float2(oacc[i][j][c2 * 2] * rz,
                                       oacc[i][j][c2 * 2 + 1] * rz);
                *reinterpret_cast<float2*>(
                    &g_mid[((size_t)t * BB + b) * EE + h * HD + d]) = v;
            }
    }
}

// ===========================================================================
// avg_weights pass: one block per (b, q-tile, k-tile). Recomputes S for all
// 8 heads (bitwise identical to fused kernel's S) and writes
// avg[b][q][k] = sum_h exp(S_h)/(8 * Z_h).
// ===========================================================================
__global__ __launch_bounds__(256, 1)
void avg_attn(float* __restrict__ avg_out)
{
    extern __shared__ uint32_t sm[];
    uint32_t* Qs = sm;
    uint32_t* Ks = sm + 128 * QS_W;

    const int kt = blockIdx.x, qt = blockIdx.y, b = blockIdx.z;
    const int tid = threadIdx.x, lane = tid & 31, warp = tid >> 5;
    const int gid = lane >> 2, tig = lane & 3;
    const int wmq = (warp >> 2) * 64, wnq = (warp & 3) * 32;

    float aacc[4][4][4];
#pragma unroll
    for (int i = 0; i < 4; i++)
#pragma unroll
        for (int j = 0; j < 4; j++)
#pragma unroll
            for (int c = 0; c < 4; c++) aacc[i][j][c] = 0.0f;

#pragma unroll 1
    for (int h = 0; h < HH; h++) {
        const int bh = b * HH + h;
        __syncthreads();
        stage64(Qs, g_q + ((size_t)bh * TT + qt * 128) * HD, tid);
        stage64(Ks, g_k + ((size_t)bh * TT + kt * 128) * HD, tid);
        __syncthreads();

        float acc[4][4][4];
#pragma unroll
        for (int i = 0; i < 4; i++)
#pragma unroll
            for (int j = 0; j < 4; j++)
#pragma unroll
                for (int c = 0; c < 4; c++) acc[i][j][c] = 0.0f;
        qk_mma(acc, Qs, Ks, wmq, wnq, gid, tig);

        float rz[4][2];
#pragma unroll
        for (int i = 0; i < 4; i++) {
            const size_t zb = (size_t)bh * TT + qt * 128 + wmq + i * 16 + gid;
            rz[i][0] = 0.125f / g_Z[zb];
            rz[i][1] = 0.125f / g_Z[zb + 8];
        }
#pragma unroll
        for (int i = 0; i < 4; i++)
#pragma unroll
            for (int j = 0; j < 4; j++)
#pragma unroll
                for (int c = 0; c < 4; c++)
                    aacc[i][j][c] += __expf(acc[i][j][c]) * rz[i][c >> 1];
    }

    // write avg tile (float2 stores: columns 2tig, 2tig+1 adjacent)
#pragma unroll
    for (int i = 0; i < 4; i++)
#pragma unroll
        for (int c2 = 0; c2 < 2; c2++) {
            const int row = qt * 128 + wmq + i * 16 + gid + c2 * 8;
#pragma unroll
            for (int j = 0; j < 4; j++) {
                const int col = kt * 128 + wnq + j * 8 + 2 * tig;
                float2 v = make_float2(aacc[i][j][c2 * 2], aacc[i][j][c2 * 2 + 1]);
                *reinterpret_cast<float2*>(
                    &avg_out[((size_t)b * TT + row) * TT + col]) = v;
            }
        }
}

// ===========================================================================
// tf32 GEMM for QKV in-projection (EPI 0) and out-projection (EPI 3).
// Unchanged from validated round-4 kernel (minus deleted EPI 1/2 paths).
// ===========================================================================
__device__ __forceinline__ int kperm(int k) {
    const int g = k >> 3, kk = k & 7;
    return g * 8 + ((kk & 3) * 2 + (kk >> 2));
}

template<int EPI, int BM, int BN, int WM, int WN, int K, int LDA, int LDB>
__global__ __launch_bounds__(256)
void mma_gemm(const float* __restrict__ Aext, const float* __restrict__ Bext,
              const float* __restrict__ bias, float* __restrict__ Cext)
{
    constexpr int BK = 16;
    constexpr int WARPS_N = BN / WN;
    constexpr int MT = WM / 16;
    constexpr int NT = WN / 8;
    static_assert((BM / WM) * (BN / WN) == 8, "8 warps");

    const int tid  = threadIdx.x;
    const int lane = tid & 31;
    const int warp = tid >> 5;
    const int wm0  = (warp / WARPS_N) * WM;
    const int wn0  = (warp % WARPS_N) * WN;
    const int m0   = blockIdx.y * BM;
    const int n0   = blockIdx.x * BN;

    const float* A  = (EPI == 0) ? Aext : g_mid;
    const float* Bm = Bext;

    __shared__ __align__(16) uint32_t As[2][BM][SPAD];
    __shared__ __align__(16) uint32_t Bs[2][BN][SPAD];

    float acc[MT][NT][4];
#pragma unroll
    for (int i = 0; i < MT; i++)
#pragma unroll
        for (int j = 0; j < NT; j++)
#pragma unroll
            for (int c = 0; c < 4; c++) acc[i][j][c] = 0.0f;

    const int lrow = tid >> 2;
    const int lcol = (tid & 3) << 2;
    const int c0 = kperm(lcol), c1 = kperm(lcol + 1),
              c2 = kperm(lcol + 2), c3 = kperm(lcol + 3);

    const int gid = lane >> 2;
    const int tig = lane & 3;

#pragma unroll
    for (int r = lrow; r < BM; r += 64) {
        float4 v = *reinterpret_cast<const float4*>(&A[(size_t)(m0 + r) * LDA + lcol]);
        As[0][r][c0] = to_tf32(v.x); As[0][r][c1] = to_tf32(v.y);
        As[0][r][c2] = to_tf32(v.z); As[0][r][c3] = to_tf32(v.w);
    }
#pragma unroll
    for (int r = lrow; r < BN; r += 64) {
        float4 v = *reinterpret_cast<const float4*>(&Bm[(size_t)(n0 + r) * LDB + lcol]);
        Bs[0][r][c0] = to_tf32(v.x); Bs[0][r][c1] = to_tf32(v.y);
        Bs[0][r][c2] = to_tf32(v.z); Bs[0][r][c3] = to_tf32(v.w);
    }
    __syncthreads();

    int buf = 0;

#pragma unroll 1
    for (int k0 = 0; k0 < K; k0 += BK) {
        const bool has_next = (k0 + BK) < K;
        float4 pa[BM / 64], pb[(BN + 63) / 64];
        if (has_next) {
#pragma unroll
            for (int q = 0; q < BM / 64; q++)
                pa[q] = *reinterpret_cast<const float4*>(
                    &A[(size_t)(m0 + lrow + q * 64) * LDA + k0 + BK + lcol]);
#pragma unroll
            for (int q = 0; q < (BN + 63) / 64; q++)
                if (lrow + q * 64 < BN)
                    pb[q] = *reinterpret_cast<const float4*>(
                        &Bm[(size_t)(n0 + lrow + q * 64) * LDB + k0 + BK + lcol]);
        }

#pragma unroll
        for (int g = 0; g < 2; g++) {
            const int kc = g * 8 + 2 * tig;
            uint2 alo[MT], ahi[MT], bfr[NT];
#pragma unroll
            for (int i = 0; i < MT; i++) {
                const int row = wm0 + i * 16 + gid;
                alo[i] = *reinterpret_cast<const uint2*>(&As[buf][row][kc]);
                ahi[i] = *reinterpret_cast<const uint2*>(&As[buf][row + 8][kc]);
            }
#pragma unroll
            for (int j = 0; j < NT; j++)
                bfr[j] = *reinterpret_cast<const uint2*>(&Bs[buf][wn0 + j * 8 + gid][kc]);
#pragma unroll
            for (int i = 0; i < MT; i++)
#pragma unroll
                for (int j = 0; j < NT; j++)
                    MMA_TF32(acc[i][j], alo[i].x, ahi[i].x, alo[i].y, ahi[i].y,
                             bfr[j].x, bfr[j].y);
        }

        if (has_next) {
            const int nb = buf ^ 1;
#pragma unroll
            for (int q = 0; q < BM / 64; q++) {
                const int r = lrow + q * 64;
                As[nb][r][c0] = to_tf32(pa[q].x); As[nb][r][c1] = to_tf32(pa[q].y);
                As[nb][r][c2] = to_tf32(pa[q].z); As[nb][r][c3] = to_tf32(pa[q].w);
            }
#pragma unroll
            for (int q = 0; q < (BN + 63) / 64; q++) {
                const int r = lrow + q * 64;
                if (r < BN) {
                    Bs[nb][r][c0] = to_tf32(pb[q].x); Bs[nb][r][c1] = to_tf32(pb[q].y);
                    Bs[nb][r][c2] = to_tf32(pb[q].z); Bs[nb][r][c3] = to_tf32(pb[q].w);
                }
            }
            __syncthreads();
            buf = nb;
        }
    }

    // Epilogue
#pragma unroll
    for (int i = 0; i < MT; i++) {
        const int rbase = m0 + wm0 + i * 16 + gid;
#pragma unroll
        for (int j = 0; j < NT; j++) {
            const int cbase = n0 + wn0 + j * 8 + tig * 2;
#pragma unroll
            for (int c = 0; c < 4; c++) {
                const int m = rbase + (c >> 1) * 8;
                const int n = cbase + (c & 1);
                float v = acc[i][j][c] + bias[n];
                if constexpr (EPI == 0) {
                    const int t = m >> 2, b = m & 3;
                    const int sec = n >> 9, h = (n >> 6) & 7, d = n & 63;
                    const int bh = b * HH + h;
                    if (sec == 0)
                        g_q[((size_t)bh * TT + t) * HD + d] = v * SCALE;
                    else if (sec == 1)
                        g_k[((size_t)bh * TT + t) * HD + d] = v;
                    else
                        g_vt[((size_t)bh * HD + d) * TT + t] = v;
                } else {
                    Cext[(size_t)m * EE + n] = v;
                }
            }
        }
    }
}

// ---------------------------------------------------------------------------
extern "C" void kernel_launch(void* const* d_in, const int* in_sizes, int n_in,
                              void* d_out, int out_size)
{
    const float* x     = (const float*)d_in[0];  // [T,B,E]
    const float* w_in  = (const float*)d_in[1];  // [3E,E]
    const float* b_in  = (const float*)d_in[2];  // [3E]
    const float* w_out = (const float*)d_in[3];  // [E,E]
    const float* b_out = (const float*)d_in[4];  // [E]

    float* out      = (float*)d_out;
    float* attn_out = out;                              // T*B*E
    float* avg_out  = out + (size_t)TT * BB * EE;       // B*T*T

    cudaFuncSetAttribute(fused_attn, cudaFuncAttributeMaxDynamicSharedMemorySize,
                         FUSED_SMEM);
    cudaFuncSetAttribute(avg_attn, cudaFuncAttributeMaxDynamicSharedMemorySize,
                         AVG_SMEM);

    // 1) QKV in-projection: [8192,512] x [1536,512]^T
    {
        dim3 grid(3 * EE / 128, (TT * BB) / 128, 1);
        mma_gemm<0, 128, 128, 64, 32, EE, EE, EE><<<grid, 256>>>(x, w_in, b_in, nullptr);
    }
    // 2) Fused attention: scores + exp + rowsum + PV, per (q-tile, head)
    {
        dim3 grid(TT / 128, BH, 1);
        fused_attn<<<grid, 256, FUSED_SMEM>>>();
    }
    // 3) avg_weights recompute pass
    {
        dim3 grid(TT / 128, TT / 128, BB);
        avg_attn<<<grid, 256, AVG_SMEM>>>(avg_out);
    }
    // 4) Out projection: [8192,512] x [512,512]^T -> d_out
    {
        dim3 grid(EE / 128, (TT * BB) / 128, 1);
        mma_gemm<3, 128, 128, 64, 32, EE, EE, EE><<<grid, 256>>>(nullptr, w_out, b_out, attn_out);
    }
}

// round 7
// speedup vs baseline: 2.2923x; 1.0427x over previous
#include <cuda_runtime.h>
#include <cstdint>
#include <cstddef>

// Problem constants
#define TT   2048
#define BB   4
#define EE   512
#define HH   8
#define HD   64
#define BH   32            // B*H
#define SCALE 0.125f       // HD^-0.5
#define SPAD 18            // smem row pad for mma_gemm (validated round 4)

// Scratch (static device allocations; no cudaMalloc allowed).
__device__ __align__(16) float g_q [(size_t)BH * TT * HD];     // [bh][t][d], pre-scaled
__device__ __align__(16) float g_k [(size_t)BH * TT * HD];     // [bh][t][d]
__device__ __align__(16) float g_vt[(size_t)BH * HD * TT];     // [bh][d][t]  (V transposed)
__device__ __align__(16) float g_mid[(size_t)TT * BB * EE];    // attn pre-projection, [t][b][e]
__device__ __align__(16) float g_Z[(size_t)BH * TT];           // softmax denominators

__device__ __forceinline__ uint32_t to_tf32(float f) {
    uint32_t r;
    asm("cvt.rna.tf32.f32 %0, %1;" : "=r"(r) : "f"(f));
    return r;
}

#define MMA_TF32(acc, a0, a1, a2, a3, b0, b1)                              \
    asm volatile(                                                          \
        "mma.sync.aligned.m16n8k8.row.col.f32.tf32.tf32.f32 "              \
        "{%0,%1,%2,%3}, {%4,%5,%6,%7}, {%8,%9}, {%0,%1,%2,%3};\n"          \
        : "+f"((acc)[0]), "+f"((acc)[1]), "+f"((acc)[2]), "+f"((acc)[3])   \
        : "r"(a0), "r"(a1), "r"(a2), "r"(a3), "r"(b0), "r"(b1))

// ===========================================================================
// Fused attention: smem layout constants (words = uint32)
// Row strides chosen so stride/2 mod 16 == 4  ->  fragment LDS.64 is
// bank-conflict-free (bank-pair = 4*gid + tig, distinct per 16-lane phase).
// ===========================================================================
constexpr int QS_W = 72;                       // stride for 64-wide k tiles
constexpr int PS_W = 136;                      // stride for 128-wide k tiles
constexpr int QS_OFF = 0;                      // Q  [128][QS_W]
constexpr int KS_OFF = QS_OFF + 128 * QS_W;    // K  [128][QS_W]
constexpr int VS_OFF = KS_OFF + 128 * QS_W;    // V^T[64][PS_W]
constexpr int PS_OFF = VS_OFF + 64 * PS_W;     // P  [128][PS_W]
constexpr int ZS_OFF = PS_OFF + 128 * PS_W;    // zsm[128] floats
constexpr int FUSED_SMEM = (ZS_OFF + 128) * 4; // 178688 B
constexpr int AVG_SMEM   = (2 * 128 * QS_W) * 4; // 73728 B

// ---------------------------------------------------------------------------
// Staging split into gmem->reg prefetch and reg->smem store (tf32 + permute).
// Permutation: logical k -> g*8 + ((k&3)*2 + ((k&7)>>2)); float4 at c4 lands
// at (c4&~7)+((c4>>2)&1) + {0,2,4,6}.
// ---------------------------------------------------------------------------
__device__ __forceinline__ void load64_regs(float4 r[8], const float* __restrict__ src,
                                            int tid)
{
#pragma unroll
    for (int rr = 0; rr < 2; rr++) {
        const int row = (tid >> 2) + rr * 64;
#pragma unroll
        for (int cc = 0; cc < 4; cc++) {
            const int c4 = ((tid & 3) + cc * 4) << 2;
            r[rr * 4 + cc] = *reinterpret_cast<const float4*>(src + row * HD + c4);
        }
    }
}
__device__ __forceinline__ void sts64(uint32_t* __restrict__ dst, const float4 r[8],
                                      int tid)
{
#pragma unroll
    for (int rr = 0; rr < 2; rr++) {
        const int row = (tid >> 2) + rr * 64;
        uint32_t* d = dst + row * QS_W;
#pragma unroll
        for (int cc = 0; cc < 4; cc++) {
            const int c4 = ((tid & 3) + cc * 4) << 2;
            uint32_t* p = d + (c4 & ~7) + ((c4 >> 2) & 1);
            const float4 v = r[rr * 4 + cc];
            p[0] = to_tf32(v.x); p[2] = to_tf32(v.y);
            p[4] = to_tf32(v.z); p[6] = to_tf32(v.w);
        }
    }
}
// V^T tile: 64 rows (d) x 128 cols (t), src row stride TT.
__device__ __forceinline__ void loadv_regs(float4 r[8], const float* __restrict__ src,
                                           int tid)
{
#pragma unroll
    for (int rr = 0; rr < 2; rr++) {
        const int d = (tid >> 3) + rr * 32;
#pragma unroll
        for (int cc = 0; cc < 4; cc++) {
            const int c4 = ((tid & 7) + cc * 8) << 2;
            r[rr * 4 + cc] = *reinterpret_cast<const float4*>(src + (size_t)d * TT + c4);
        }
    }
}
__device__ __forceinline__ void stsv(uint32_t* __restrict__ dst, const float4 r[8],
                                     int tid)
{
#pragma unroll
    for (int rr = 0; rr < 2; rr++) {
        const int d = (tid >> 3) + rr * 32;
        uint32_t* dd = dst + d * PS_W;
#pragma unroll
        for (int cc = 0; cc < 4; cc++) {
            const int c4 = ((tid & 7) + cc * 8) << 2;
            uint32_t* p = dd + (c4 & ~7) + ((c4 >> 2) & 1);
            const float4 v = r[rr * 4 + cc];
            p[0] = to_tf32(v.x); p[2] = to_tf32(v.y);
            p[4] = to_tf32(v.z); p[6] = to_tf32(v.w);
        }
    }
}

// ---------------------------------------------------------------------------
// 128x128x64 QK^T mma, warp tile 64x32 (2x4 warps), MT=4, NT=4.
// Fragment loads double-buffered: LDS for group g+1 overlaps mmas of group g.
// ---------------------------------------------------------------------------
__device__ __forceinline__ void qk_frag_load(uint2 alo[4], uint2 ahi[4], uint2 bfr[4],
                                             const uint32_t* __restrict__ Qs,
                                             const uint32_t* __restrict__ Ks,
                                             int g, int wmq, int wnq, int gid, int tig)
{
    const int kc = g * 8 + 2 * tig;
#pragma unroll
    for (int i = 0; i < 4; i++) {
        const int row = wmq + i * 16 + gid;
        alo[i] = *reinterpret_cast<const uint2*>(Qs + row * QS_W + kc);
        ahi[i] = *reinterpret_cast<const uint2*>(Qs + (row + 8) * QS_W + kc);
    }
#pragma unroll
    for (int j = 0; j < 4; j++)
        bfr[j] = *reinterpret_cast<const uint2*>(Ks + (wnq + j * 8 + gid) * QS_W + kc);
}

__device__ __forceinline__ void qk_mma(float acc[4][4][4],
                                       const uint32_t* __restrict__ Qs,
                                       const uint32_t* __restrict__ Ks,
                                       int wmq, int wnq, int gid, int tig)
{
    uint2 alo[2][4], ahi[2][4], bfr[2][4];
    qk_frag_load(alo[0], ahi[0], bfr[0], Qs, Ks, 0, wmq, wnq, gid, tig);
#pragma unroll
    for (int g = 0; g < 8; g++) {
        const int cur = g & 1;
        if (g < 7)
            qk_frag_load(alo[cur ^ 1], ahi[cur ^ 1], bfr[cur ^ 1],
                         Qs, Ks, g + 1, wmq, wnq, gid, tig);
#pragma unroll
        for (int i = 0; i < 4; i++)
#pragma unroll
            for (int j = 0; j < 4; j++)
                MMA_TF32(acc[i][j], alo[cur][i].x, ahi[cur][i].x,
                         alo[cur][i].y, ahi[cur][i].y,
                         bfr[cur][j].x, bfr[cur][j].y);
    }
}

// ===========================================================================
// Fused attention kernel: one block per (bh, q-tile of 128).
// ===========================================================================
__global__ __launch_bounds__(256, 1)
void fused_attn()
{
    extern __shared__ uint32_t sm[];
    uint32_t* Qs = sm + QS_OFF;
    uint32_t* Ks = sm + KS_OFF;
    uint32_t* Vs = sm + VS_OFF;
    uint32_t* Ps = sm + PS_OFF;
    float* zsm = reinterpret_cast<float*>(sm + ZS_OFF);

    const int qt = blockIdx.x, bh = blockIdx.y;
    const int tid = threadIdx.x, lane = tid & 31, warp = tid >> 5;
    const int gid = lane >> 2, tig = lane & 3;
    const int wmq = (warp >> 2) * 64, wnq = (warp & 3) * 32;   // QK phase
    const int wmp = (warp >> 1) * 32, wnp = (warp & 1) * 32;   // PV phase

    if (tid < 128) zsm[tid] = 0.0f;
    {   // stage Q once (load + store fused; only happens once)
        float4 q[8];
        load64_regs(q, g_q + ((size_t)bh * TT + qt * 128) * HD, tid);
        sts64(Qs, q, tid);
    }

    float oacc[2][4][4];
    float zacc[4][2];
#pragma unroll
    for (int i = 0; i < 2; i++)
#pragma unroll
        for (int j = 0; j < 4; j++)
#pragma unroll
            for (int c = 0; c < 4; c++) oacc[i][j][c] = 0.0f;
#pragma unroll
    for (int i = 0; i < 4; i++) { zacc[i][0] = 0.0f; zacc[i][1] = 0.0f; }

    const float* Kbase = g_k + (size_t)bh * TT * HD;
    const float* Vbase = g_vt + (size_t)bh * HD * TT;

    // Prefetch kt=0 K/V into registers
    float4 kreg[8], vreg[8];
    load64_regs(kreg, Kbase, tid);
    loadv_regs(vreg, Vbase, tid);

#pragma unroll 1
    for (int kt = 0; kt < 16; kt++) {
        __syncthreads();   // previous iter's consumers done with Ks/Vs
        sts64(Ks, kreg, tid);
        stsv(Vs, vreg, tid);
        __syncthreads();

        // ---- S = Q K^T for this k-tile ----
        float acc[4][4][4];
#pragma unroll
        for (int i = 0; i < 4; i++)
#pragma unroll
            for (int j = 0; j < 4; j++)
#pragma unroll
                for (int c = 0; c < 4; c++) acc[i][j][c] = 0.0f;
        qk_mma(acc, Qs, Ks, wmq, wnq, gid, tig);

        // ---- exp(S) -> Ps (tf32), accumulate Z partials ----
#pragma unroll
        for (int i = 0; i < 4; i++)
#pragma unroll
            for (int c2 = 0; c2 < 2; c2++) {
                const int row = wmq + i * 16 + gid + c2 * 8;
                uint32_t* prow = Ps + row * PS_W;
                float zp = 0.0f;
#pragma unroll
                for (int j = 0; j < 4; j++)
#pragma unroll
                    for (int c1 = 0; c1 < 2; c1++) {
                        const float e = __expf(acc[i][j][c2 * 2 + c1]);
                        const int kk = 2 * tig + c1;
                        prow[wnq + j * 8 + ((kk & 3) * 2) + (kk >> 2)] = to_tf32(e);
                        zp += e;
                    }
                zacc[i][c2] += zp;
            }
        __syncthreads();   // Ps complete

        // ---- prefetch next k-tile's K/V (overlaps PV mma below) ----
        if (kt + 1 < 16) {
            load64_regs(kreg, Kbase + (size_t)(kt + 1) * 128 * HD, tid);
            loadv_regs(vreg, Vbase + (kt + 1) * 128, tid);
        }

        // ---- O += P V : M128 x N64 x K128, warp tile 32x32, MT=2, NT=4 ----
        {
            uint2 alo[2][2], ahi[2][2], bfr[2][4];
            // load group 0 fragments
            {
                const int kc = 2 * tig;
#pragma unroll
                for (int i = 0; i < 2; i++) {
                    const int row = wmp + i * 16 + gid;
                    alo[0][i] = *reinterpret_cast<const uint2*>(Ps + row * PS_W + kc);
                    ahi[0][i] = *reinterpret_cast<const uint2*>(Ps + (row + 8) * PS_W + kc);
                }
#pragma unroll
                for (int j = 0; j < 4; j++)
                    bfr[0][j] = *reinterpret_cast<const uint2*>(Vs + (wnp + j * 8 + gid) * PS_W + kc);
            }
#pragma unroll
            for (int g = 0; g < 16; g++) {
                const int cur = g & 1;
                if (g < 15) {
                    const int kc = (g + 1) * 8 + 2 * tig;
                    const int nb = cur ^ 1;
#pragma unroll
                    for (int i = 0; i < 2; i++) {
                        const int row = wmp + i * 16 + gid;
                        alo[nb][i] = *reinterpret_cast<const uint2*>(Ps + row * PS_W + kc);
                        ahi[nb][i] = *reinterpret_cast<const uint2*>(Ps + (row + 8) * PS_W + kc);
                    }
#pragma unroll
                    for (int j = 0; j < 4; j++)
                        bfr[nb][j] = *reinterpret_cast<const uint2*>(Vs + (wnp + j * 8 + gid) * PS_W + kc);
                }
#pragma unroll
                for (int i = 0; i < 2; i++)
#pragma unroll
                    for (int j = 0; j < 4; j++)
                        MMA_TF32(oacc[i][j], alo[cur][i].x, ahi[cur][i].x,
                                 alo[cur][i].y, ahi[cur][i].y,
                                 bfr[cur][j].x, bfr[cur][j].y);
            }
        }
    }

    // ---- Z reduction across lanes/warps ----
#pragma unroll
    for (int i = 0; i < 4; i++) {
        atomicAdd(&zsm[wmq + i * 16 + gid],     zacc[i][0]);
        atomicAdd(&zsm[wmq + i * 16 + gid + 8], zacc[i][1]);
    }
    __syncthreads();
    if (tid < 128) g_Z[(size_t)bh * TT + qt * 128 + tid] = zsm[tid];

    // ---- epilogue: O / Z -> g_mid [t][b][e] ----
    const int b = bh >> 3, h = bh & 7;
#pragma unroll
    for (int i = 0; i < 2; i++) {
        const int r0 = wmp + i * 16 + gid;
        const float rz0 = 1.0f / zsm[r0];
        const float rz1 = 1.0f / zsm[r0 + 8];
#pragma unroll
        for (int j = 0; j < 4; j++)
#pragma unroll
            for (int c2 = 0; c2 < 2; c2++) {
                const int rowl = r0 + c2 * 8;
                const int d = wnp + j * 8 + 2 * tig;
                const int t = qt * 128 + rowl;
                const float rz = c2 ? rz1 : rz0;
                float2 v = make_float2(oacc[i][j][c2 * 2] * rz,
                                       oacc[i][j][c2 * 2 + 1] * rz);
                *reinterpret_cast<float2*>(
                    &g_mid[((size_t)t * BB + b) * EE + h * HD + d]) = v;
            }
    }
}

// ===========================================================================
// avg_weights pass: one block per (b, q-tile, k-tile). Recomputes S for all
// 8 heads (bitwise identical to fused kernel's S) and writes
// avg[b][q][k] = sum_h exp(S_h)/(8 * Z_h).
// ===========================================================================
__global__ __launch_bounds__(256, 1)
void avg_attn(float* __restrict__ avg_out)
{
    extern __shared__ uint32_t sm[];
    uint32_t* Qs = sm;
    uint32_t* Ks = sm + 128 * QS_W;

    const int kt = blockIdx.x, qt = blockIdx.y, b = blockIdx.z;
    const int tid = threadIdx.x, lane = tid & 31, warp = tid >> 5;
    const int gid = lane >> 2, tig = lane & 3;
    const int wmq = (warp >> 2) * 64, wnq = (warp & 3) * 32;

    float aacc[4][4][4];
#pragma unroll
    for (int i = 0; i < 4; i++)
#pragma unroll
        for (int j = 0; j < 4; j++)
#pragma unroll
            for (int c = 0; c < 4; c++) aacc[i][j][c] = 0.0f;

    // Prefetch head 0 Q/K into registers
    float4 qreg[8], kreg[8];
    load64_regs(qreg, g_q + ((size_t)(b * HH) * TT + qt * 128) * HD, tid);
    load64_regs(kreg, g_k + ((size_t)(b * HH) * TT + kt * 128) * HD, tid);

#pragma unroll 1
    for (int h = 0; h < HH; h++) {
        const int bh = b * HH + h;
        __syncthreads();
        sts64(Qs, qreg, tid);
        sts64(Ks, kreg, tid);
        __syncthreads();

        float acc[4][4][4];
#pragma unroll
        for (int i = 0; i < 4; i++)
#pragma unroll
            for (int j = 0; j < 4; j++)
#pragma unroll
                for (int c = 0; c < 4; c++) acc[i][j][c] = 0.0f;
        qk_mma(acc, Qs, Ks, wmq, wnq, gid, tig);

        // prefetch next head (overlaps the exp/accumulate phase below)
        if (h + 1 < HH) {
            const int bh2 = bh + 1;
            load64_regs(qreg, g_q + ((size_t)bh2 * TT + qt * 128) * HD, tid);
            load64_regs(kreg, g_k + ((size_t)bh2 * TT + kt * 128) * HD, tid);
        }

        float rz[4][2];
#pragma unroll
        for (int i = 0; i < 4; i++) {
            const size_t zb = (size_t)bh * TT + qt * 128 + wmq + i * 16 + gid;
            rz[i][0] = 0.125f / g_Z[zb];
            rz[i][1] = 0.125f / g_Z[zb + 8];
        }
#pragma unroll
        for (int i = 0; i < 4; i++)
#pragma unroll
            for (int j = 0; j < 4; j++)
#pragma unroll
                for (int c = 0; c < 4; c++)
                    aacc[i][j][c] += __expf(acc[i][j][c]) * rz[i][c >> 1];
    }

    // write avg tile (float2 stores: columns 2tig, 2tig+1 adjacent)
#pragma unroll
    for (int i = 0; i < 4; i++)
#pragma unroll
        for (int c2 = 0; c2 < 2; c2++) {
            const int row = qt * 128 + wmq + i * 16 + gid + c2 * 8;
#pragma unroll
            for (int j = 0; j < 4; j++) {
                const int col = kt * 128 + wnq + j * 8 + 2 * tig;
                float2 v = make_float2(aacc[i][j][c2 * 2], aacc[i][j][c2 * 2 + 1]);
                *reinterpret_cast<float2*>(
                    &avg_out[((size_t)b * TT + row) * TT + col]) = v;
            }
        }
}

// ===========================================================================
// tf32 GEMM for QKV in-projection (EPI 0) and out-projection (EPI 3).
// Unchanged (validated rounds 4/6).
// ===========================================================================
__device__ __forceinline__ int kperm(int k) {
    const int g = k >> 3, kk = k & 7;
    return g * 8 + ((kk & 3) * 2 + (kk >> 2));
}

template<int EPI, int BM, int BN, int WM, int WN, int K, int LDA, int LDB>
__global__ __launch_bounds__(256)
void mma_gemm(const float* __restrict__ Aext, const float* __restrict__ Bext,
              const float* __restrict__ bias, float* __restrict__ Cext)
{
    constexpr int BK = 16;
    constexpr int WARPS_N = BN / WN;
    constexpr int MT = WM / 16;
    constexpr int NT = WN / 8;
    static_assert((BM / WM) * (BN / WN) == 8, "8 warps");

    const int tid  = threadIdx.x;
    const int lane = tid & 31;
    const int warp = tid >> 5;
    const int wm0  = (warp / WARPS_N) * WM;
    const int wn0  = (warp % WARPS_N) * WN;
    const int m0   = blockIdx.y * BM;
    const int n0   = blockIdx.x * BN;

    const float* A  = (EPI == 0) ? Aext : g_mid;
    const float* Bm = Bext;

    __shared__ __align__(16) uint32_t As[2][BM][SPAD];
    __shared__ __align__(16) uint32_t Bs[2][BN][SPAD];

    float acc[MT][NT][4];
#pragma unroll
    for (int i = 0; i < MT; i++)
#pragma unroll
        for (int j = 0; j < NT; j++)
#pragma unroll
            for (int c = 0; c < 4; c++) acc[i][j][c] = 0.0f;

    const int lrow = tid >> 2;
    const int lcol = (tid & 3) << 2;
    const int c0 = kperm(lcol), c1 = kperm(lcol + 1),
              c2 = kperm(lcol + 2), c3 = kperm(lcol + 3);

    const int gid = lane >> 2;
    const int tig = lane & 3;

#pragma unroll
    for (int r = lrow; r < BM; r += 64) {
        float4 v = *reinterpret_cast<const float4*>(&A[(size_t)(m0 + r) * LDA + lcol]);
        As[0][r][c0] = to_tf32(v.x); As[0][r][c1] = to_tf32(v.y);
        As[0][r][c2] = to_tf32(v.z); As[0][r][c3] = to_tf32(v.w);
    }
#pragma unroll
    for (int r = lrow; r < BN; r += 64) {
        float4 v = *reinterpret_cast<const float4*>(&Bm[(size_t)(n0 + r) * LDB + lcol]);
        Bs[0][r][c0] = to_tf32(v.x); Bs[0][r][c1] = to_tf32(v.y);
        Bs[0][r][c2] = to_tf32(v.z); Bs[0][r][c3] = to_tf32(v.w);
    }
    __syncthreads();

    int buf = 0;

#pragma unroll 1
    for (int k0 = 0; k0 < K; k0 += BK) {
        const bool has_next = (k0 + BK) < K;
        float4 pa[BM / 64], pb[(BN + 63) / 64];
        if (has_next) {
#pragma unroll
            for (int q = 0; q < BM / 64; q++)
                pa[q] = *reinterpret_cast<const float4*>(
                    &A[(size_t)(m0 + lrow + q * 64) * LDA + k0 + BK + lcol]);
#pragma unroll
            for (int q = 0; q < (BN + 63) / 64; q++)
                if (lrow + q * 64 < BN)
                    pb[q] = *reinterpret_cast<const float4*>(
                        &Bm[(size_t)(n0 + lrow + q * 64) * LDB + k0 + BK + lcol]);
        }

#pragma unroll
        for (int g = 0; g < 2; g++) {
            const int kc = g * 8 + 2 * tig;
            uint2 alo[MT], ahi[MT], bfr[NT];
#pragma unroll
            for (int i = 0; i < MT; i++) {
                const int row = wm0 + i * 16 + gid;
                alo[i] = *reinterpret_cast<const uint2*>(&As[buf][row][kc]);
                ahi[i] = *reinterpret_cast<const uint2*>(&As[buf][row + 8][kc]);
            }
#pragma unroll
            for (int j = 0; j < NT; j++)
                bfr[j] = *reinterpret_cast<const uint2*>(&Bs[buf][wn0 + j * 8 + gid][kc]);
#pragma unroll
            for (int i = 0; i < MT; i++)
#pragma unroll
                for (int j = 0; j < NT; j++)
                    MMA_TF32(acc[i][j], alo[i].x, ahi[i].x, alo[i].y, ahi[i].y,
                             bfr[j].x, bfr[j].y);
        }

        if (has_next) {
            const int nb = buf ^ 1;
#pragma unroll
            for (int q = 0; q < BM / 64; q++) {
                const int r = lrow + q * 64;
                As[nb][r][c0] = to_tf32(pa[q].x); As[nb][r][c1] = to_tf32(pa[q].y);
                As[nb][r][c2] = to_tf32(pa[q].z); As[nb][r][c3] = to_tf32(pa[q].w);
            }
#pragma unroll
            for (int q = 0; q < (BN + 63) / 64; q++) {
                const int r = lrow + q * 64;
                if (r < BN) {
                    Bs[nb][r][c0] = to_tf32(pb[q].x); Bs[nb][r][c1] = to_tf32(pb[q].y);
                    Bs[nb][r][c2] = to_tf32(pb[q].z); Bs[nb][r][c3] = to_tf32(pb[q].w);
                }
            }
            __syncthreads();
            buf = nb;
        }
    }

    // Epilogue
#pragma unroll
    for (int i = 0; i < MT; i++) {
        const int rbase = m0 + wm0 + i * 16 + gid;
#pragma unroll
        for (int j = 0; j < NT; j++) {
            const int cbase = n0 + wn0 + j * 8 + tig * 2;
#pragma unroll
            for (int c = 0; c < 4; c++) {
                const int m = rbase + (c >> 1) * 8;
                const int n = cbase + (c & 1);
                float v = acc[i][j][c] + bias[n];
                if constexpr (EPI == 0) {
                    const int t = m >> 2, b = m & 3;
                    const int sec = n >> 9, h = (n >> 6) & 7, d = n & 63;
                    const int bh = b * HH + h;
                    if (sec == 0)
                        g_q[((size_t)bh * TT + t) * HD + d] = v * SCALE;
                    else if (sec == 1)
                        g_k[((size_t)bh * TT + t) * HD + d] = v;
                    else
                        g_vt[((size_t)bh * HD + d) * TT + t] = v;
                } else {
                    Cext[(size_t)m * EE + n] = v;
                }
            }
        }
    }
}

// ---------------------------------------------------------------------------
extern "C" void kernel_launch(void* const* d_in, const int* in_sizes, int n_in,
                              void* d_out, int out_size)
{
    const float* x     = (const float*)d_in[0];  // [T,B,E]
    const float* w_in  = (const float*)d_in[1];  // [3E,E]
    const float* b_in  = (const float*)d_in[2];  // [3E]
    const float* w_out = (const float*)d_in[3];  // [E,E]
    const float* b_out = (const float*)d_in[4];  // [E]

    float* out      = (float*)d_out;
    float* attn_out = out;                              // T*B*E
    float* avg_out  = out + (size_t)TT * BB * EE;       // B*T*T

    cudaFuncSetAttribute(fused_attn, cudaFuncAttributeMaxDynamicSharedMemorySize,
                         FUSED_SMEM);
    cudaFuncSetAttribute(avg_attn, cudaFuncAttributeMaxDynamicSharedMemorySize,
                         AVG_SMEM);

    // 1) QKV in-projection: [8192,512] x [1536,512]^T
    {
        dim3 grid(3 * EE / 128, (TT * BB) / 128, 1);
        mma_gemm<0, 128, 128, 64, 32, EE, EE, EE><<<grid, 256>>>(x, w_in, b_in, nullptr);
    }
    // 2) Fused attention: scores + exp + rowsum + PV, per (q-tile, head)
    {
        dim3 grid(TT / 128, BH, 1);
        fused_attn<<<grid, 256, FUSED_SMEM>>>();
    }
    // 3) avg_weights recompute pass
    {
        dim3 grid(TT / 128, TT / 128, BB);
        avg_attn<<<grid, 256, AVG_SMEM>>>(avg_out);
    }
    // 4) Out projection: [8192,512] x [512,512]^T -> d_out
    {
        dim3 grid(EE / 128, (TT * BB) / 128, 1);
        mma_gemm<3, 128, 128, 64, 32, EE, EE, EE><<<grid, 256>>>(nullptr, w_out, b_out, attn_out);
    }
}

// round 8
// speedup vs baseline: 2.4225x; 1.0568x over previous
#include <cuda_runtime.h>
#include <cstdint>
#include <cstddef>

// Problem constants
#define TT   2048
#define BB   4
#define EE   512
#define HH   8
#define HD   64
#define BH   32            // B*H
#define SCALE 0.125f       // HD^-0.5
#define SPAD 18            // smem row pad for mma_gemm (validated round 4)

// Scratch (static device allocations; no cudaMalloc allowed).
__device__ __align__(16) float g_q [(size_t)BH * TT * HD];     // [bh][t][d], pre-scaled
__device__ __align__(16) float g_k [(size_t)BH * TT * HD];     // [bh][t][d]
__device__ __align__(16) float g_vt[(size_t)BH * HD * TT];     // [bh][d][t]  (V transposed)
__device__ __align__(16) float g_mid[(size_t)TT * BB * EE];    // attn pre-projection, [t][b][e]
__device__ __align__(16) float g_Z[(size_t)BH * TT];           // softmax denominators

__device__ __forceinline__ uint32_t to_tf32(float f) {
    uint32_t r;
    asm("cvt.rna.tf32.f32 %0, %1;" : "=r"(r) : "f"(f));
    return r;
}

#define MMA_TF32(acc, a0, a1, a2, a3, b0, b1)                              \
    asm volatile(                                                          \
        "mma.sync.aligned.m16n8k8.row.col.f32.tf32.tf32.f32 "              \
        "{%0,%1,%2,%3}, {%4,%5,%6,%7}, {%8,%9}, {%0,%1,%2,%3};\n"          \
        : "+f"((acc)[0]), "+f"((acc)[1]), "+f"((acc)[2]), "+f"((acc)[3])   \
        : "r"(a0), "r"(a1), "r"(a2), "r"(a3), "r"(b0), "r"(b1))

// ===========================================================================
// smem layout constants (words = uint32). Row strides: stride/2 mod 16 == 4
// -> fragment LDS.64 bank-conflict-free.
// ===========================================================================
constexpr int QS_W = 72;                       // stride for 64-wide k tiles
constexpr int PS_W = 136;                      // stride for 128-wide k tiles
constexpr int FUSED_SMEM = (128 * QS_W + 64 * PS_W) * 4;   // K + V^T = 71680 B
constexpr int AVG_SMEM   = (2 * 128 * QS_W) * 4;           // 73728 B

// ---------------------------------------------------------------------------
// Staging: gmem->reg and reg->smem (tf32 + k8-group permutation).
// Permutation: logical k -> g*8 + ((k&3)*2 + ((k&7)>>2)); float4 at c4 lands
// at (c4&~7)+((c4>>2)&1) + {0,2,4,6}.
// ---------------------------------------------------------------------------
__device__ __forceinline__ void load64_regs(float4 r[8], const float* __restrict__ src,
                                            int tid)
{
#pragma unroll
    for (int rr = 0; rr < 2; rr++) {
        const int row = (tid >> 2) + rr * 64;
#pragma unroll
        for (int cc = 0; cc < 4; cc++) {
            const int c4 = ((tid & 3) + cc * 4) << 2;
            r[rr * 4 + cc] = *reinterpret_cast<const float4*>(src + row * HD + c4);
        }
    }
}
__device__ __forceinline__ void sts64(uint32_t* __restrict__ dst, const float4 r[8],
                                      int tid)
{
#pragma unroll
    for (int rr = 0; rr < 2; rr++) {
        const int row = (tid >> 2) + rr * 64;
        uint32_t* d = dst + row * QS_W;
#pragma unroll
        for (int cc = 0; cc < 4; cc++) {
            const int c4 = ((tid & 3) + cc * 4) << 2;
            uint32_t* p = d + (c4 & ~7) + ((c4 >> 2) & 1);
            const float4 v = r[rr * 4 + cc];
            p[0] = to_tf32(v.x); p[2] = to_tf32(v.y);
            p[4] = to_tf32(v.z); p[6] = to_tf32(v.w);
        }
    }
}
// V^T tile: 64 rows (d) x 128 cols (t), src row stride TT.
__device__ __forceinline__ void loadv_regs(float4 r[8], const float* __restrict__ src,
                                           int tid)
{
#pragma unroll
    for (int rr = 0; rr < 2; rr++) {
        const int d = (tid >> 3) + rr * 32;
#pragma unroll
        for (int cc = 0; cc < 4; cc++) {
            const int c4 = ((tid & 7) + cc * 8) << 2;
            r[rr * 4 + cc] = *reinterpret_cast<const float4*>(src + (size_t)d * TT + c4);
        }
    }
}
__device__ __forceinline__ void stsv(uint32_t* __restrict__ dst, const float4 r[8],
                                     int tid)
{
#pragma unroll
    for (int rr = 0; rr < 2; rr++) {
        const int d = (tid >> 3) + rr * 32;
        uint32_t* dd = dst + d * PS_W;
#pragma unroll
        for (int cc = 0; cc < 4; cc++) {
            const int c4 = ((tid & 7) + cc * 8) << 2;
            uint32_t* p = dd + (c4 & ~7) + ((c4 >> 2) & 1);
            const float4 v = r[rr * 4 + cc];
            p[0] = to_tf32(v.x); p[2] = to_tf32(v.y);
            p[4] = to_tf32(v.z); p[6] = to_tf32(v.w);
        }
    }
}

// ---------------------------------------------------------------------------
// 128x128x64 QK^T mma for avg_attn: warp tile 64x32, MT=4, NT=4, with
// fragment double-buffering (validated round 7).
// ---------------------------------------------------------------------------
__device__ __forceinline__ void qk_frag_load(uint2 alo[4], uint2 ahi[4], uint2 bfr[4],
                                             const uint32_t* __restrict__ Qs,
                                             const uint32_t* __restrict__ Ks,
                                             int g, int wmq, int wnq, int gid, int tig)
{
    const int kc = g * 8 + 2 * tig;
#pragma unroll
    for (int i = 0; i < 4; i++) {
        const int row = wmq + i * 16 + gid;
        alo[i] = *reinterpret_cast<const uint2*>(Qs + row * QS_W + kc);
        ahi[i] = *reinterpret_cast<const uint2*>(Qs + (row + 8) * QS_W + kc);
    }
#pragma unroll
    for (int j = 0; j < 4; j++)
        bfr[j] = *reinterpret_cast<const uint2*>(Ks + (wnq + j * 8 + gid) * QS_W + kc);
}

__device__ __forceinline__ void qk_mma(float acc[4][4][4],
                                       const uint32_t* __restrict__ Qs,
                                       const uint32_t* __restrict__ Ks,
                                       int wmq, int wnq, int gid, int tig)
{
    uint2 alo[2][4], ahi[2][4], bfr[2][4];
    qk_frag_load(alo[0], ahi[0], bfr[0], Qs, Ks, 0, wmq, wnq, gid, tig);
#pragma unroll
    for (int g = 0; g < 8; g++) {
        const int cur = g & 1;
        if (g < 7)
            qk_frag_load(alo[cur ^ 1], ahi[cur ^ 1], bfr[cur ^ 1],
                         Qs, Ks, g + 1, wmq, wnq, gid, tig);
#pragma unroll
        for (int i = 0; i < 4; i++)
#pragma unroll
            for (int j = 0; j < 4; j++)
                MMA_TF32(acc[i][j], alo[cur][i].x, ahi[cur][i].x,
                         alo[cur][i].y, ahi[cur][i].y,
                         bfr[cur][j].x, bfr[cur][j].y);
    }
}

// ===========================================================================
// Fused attention v2: one block per (bh, q-tile of 128), 8 warps, each warp
// owns 16 q-rows end-to-end. S and P live in registers; P reaches the PV mma
// via quad shuffles (C-frag -> A-frag). smem holds only K + V^T -> 2 CTAs/SM.
// ===========================================================================
__global__ __launch_bounds__(256, 2)
void fused_attn()
{
    extern __shared__ uint32_t sm[];
    uint32_t* Ks = sm;                    // [128][QS_W]
    uint32_t* Vs = sm + 128 * QS_W;       // [64][PS_W]

    const int qt = blockIdx.x, bh = blockIdx.y;
    const int tid = threadIdx.x, lane = tid & 31, warp = tid >> 5;
    const int gid = lane >> 2, tig = lane & 3;
    const int r0 = warp * 16 + gid;       // this lane's low row within tile

    // ---- stage Q once through the Ks buffer, pull A-fragments to regs ----
    uint32_t qa[8][4];
    {
        float4 q[8];
        load64_regs(q, g_q + ((size_t)bh * TT + qt * 128) * HD, tid);
        sts64(Ks, q, tid);
        __syncthreads();
#pragma unroll
        for (int g = 0; g < 8; g++) {
            const int kc = g * 8 + 2 * tig;
            uint2 lo = *reinterpret_cast<const uint2*>(Ks + r0 * QS_W + kc);
            uint2 hi = *reinterpret_cast<const uint2*>(Ks + (r0 + 8) * QS_W + kc);
            qa[g][0] = lo.x; qa[g][1] = hi.x; qa[g][2] = lo.y; qa[g][3] = hi.y;
        }
        __syncthreads();
    }

    float oacc[8][4];
#pragma unroll
    for (int j = 0; j < 8; j++)
#pragma unroll
        for (int c = 0; c < 4; c++) oacc[j][c] = 0.0f;
    float zr0 = 0.0f, zr1 = 0.0f;

    const float* Kbase = g_k + (size_t)bh * TT * HD;
    const float* Vbase = g_vt + (size_t)bh * HD * TT;

#pragma unroll 1
    for (int kt = 0; kt < 16; kt++) {
        __syncthreads();   // prior iter's consumers done with Ks/Vs
        {
            float4 kr[8];
            load64_regs(kr, Kbase + (size_t)kt * 128 * HD, tid);
            sts64(Ks, kr, tid);
        }
        {
            float4 vr[8];
            loadv_regs(vr, Vbase + kt * 128, tid);
            stsv(Vs, vr, tid);
        }
        __syncthreads();

#pragma unroll 1
        for (int half = 0; half < 2; half++) {
            // ---- S half: rows [16w,16w+16), cols [64*half, 64*half+64) ----
            float acc[8][4];
#pragma unroll
            for (int jj = 0; jj < 8; jj++)
#pragma unroll
                for (int c = 0; c < 4; c++) acc[jj][c] = 0.0f;

#pragma unroll
            for (int g = 0; g < 8; g++) {
#pragma unroll
                for (int jj = 0; jj < 8; jj++) {
                    const int j = half * 8 + jj;
                    uint2 b = *reinterpret_cast<const uint2*>(
                        Ks + (8 * j + gid) * QS_W + 8 * g + 2 * tig);
                    MMA_TF32(acc[jj], qa[g][0], qa[g][1], qa[g][2], qa[g][3],
                             b.x, b.y);
                }
            }

            // ---- exp, Z, C-frag -> A-frag shuffle, PV mma ----
#pragma unroll
            for (int jj = 0; jj < 8; jj++) {
                const int g = half * 8 + jj;       // PV k-group = S n-tile
                const float e0 = __expf(acc[jj][0]);
                const float e1 = __expf(acc[jj][1]);
                const float e2 = __expf(acc[jj][2]);
                const float e3 = __expf(acc[jj][3]);
                zr0 += e0 + e1;
                zr1 += e2 + e3;

                const int s0 = (lane & ~3) | (tig >> 1);
                const int s1 = s0 + 2;
                const float p00 = __shfl_sync(0xffffffffu, e0, s0);
                const float p01 = __shfl_sync(0xffffffffu, e1, s0);
                const float p10 = __shfl_sync(0xffffffffu, e2, s0);
                const float p11 = __shfl_sync(0xffffffffu, e3, s0);
                const float q00 = __shfl_sync(0xffffffffu, e0, s1);
                const float q01 = __shfl_sync(0xffffffffu, e1, s1);
                const float q10 = __shfl_sync(0xffffffffu, e2, s1);
                const float q11 = __shfl_sync(0xffffffffu, e3, s1);
                const bool odd = (tig & 1) != 0;
                const uint32_t a0 = to_tf32(odd ? p01 : p00);
                const uint32_t a1 = to_tf32(odd ? p11 : p10);
                const uint32_t a2 = to_tf32(odd ? q01 : q00);
                const uint32_t a3 = to_tf32(odd ? q11 : q10);

#pragma unroll
                for (int j2 = 0; j2 < 8; j2++) {
                    uint2 b = *reinterpret_cast<const uint2*>(
                        Vs + (8 * j2 + gid) * PS_W + 8 * g + 2 * tig);
                    MMA_TF32(oacc[j2], a0, a1, a2, a3, b.x, b.y);
                }
            }
        }
    }

    // ---- Z: reduce over quad (rows are warp-exclusive; no smem needed) ----
    zr0 += __shfl_xor_sync(0xffffffffu, zr0, 1);
    zr0 += __shfl_xor_sync(0xffffffffu, zr0, 2);
    zr1 += __shfl_xor_sync(0xffffffffu, zr1, 1);
    zr1 += __shfl_xor_sync(0xffffffffu, zr1, 2);
    if (tig == 0) {
        g_Z[(size_t)bh * TT + qt * 128 + r0]     = zr0;
        g_Z[(size_t)bh * TT + qt * 128 + r0 + 8] = zr1;
    }

    // ---- epilogue: O / Z -> g_mid [t][b][e] ----
    const int b = bh >> 3, h = bh & 7;
    const float rz0 = 1.0f / zr0;
    const float rz1 = 1.0f / zr1;
#pragma unroll
    for (int j2 = 0; j2 < 8; j2++) {
        const int d = h * HD + j2 * 8 + 2 * tig;
        const int t0 = qt * 128 + r0;
        float2 v0 = make_float2(oacc[j2][0] * rz0, oacc[j2][1] * rz0);
        float2 v1 = make_float2(oacc[j2][2] * rz1, oacc[j2][3] * rz1);
        *reinterpret_cast<float2*>(&g_mid[((size_t)t0 * BB + b) * EE + d])       = v0;
        *reinterpret_cast<float2*>(&g_mid[((size_t)(t0 + 8) * BB + b) * EE + d]) = v1;
    }
}

// ===========================================================================
// avg_weights pass (unchanged, validated round 7): one block per
// (b, q-tile, k-tile); recomputes S for all 8 heads (bitwise identical) and
// writes avg[b][q][k] = sum_h exp(S_h)/(8 * Z_h).
// ===========================================================================
__global__ __launch_bounds__(256, 1)
void avg_attn(float* __restrict__ avg_out)
{
    extern __shared__ uint32_t sm[];
    uint32_t* Qs = sm;
    uint32_t* Ks = sm + 128 * QS_W;

    const int kt = blockIdx.x, qt = blockIdx.y, b = blockIdx.z;
    const int tid = threadIdx.x, lane = tid & 31, warp = tid >> 5;
    const int gid = lane >> 2, tig = lane & 3;
    const int wmq = (warp >> 2) * 64, wnq = (warp & 3) * 32;

    float aacc[4][4][4];
#pragma unroll
    for (int i = 0; i < 4; i++)
#pragma unroll
        for (int j = 0; j < 4; j++)
#pragma unroll
            for (int c = 0; c < 4; c++) aacc[i][j][c] = 0.0f;

    float4 qreg[8], kreg[8];
    load64_regs(qreg, g_q + ((size_t)(b * HH) * TT + qt * 128) * HD, tid);
    load64_regs(kreg, g_k + ((size_t)(b * HH) * TT + kt * 128) * HD, tid);

#pragma unroll 1
    for (int h = 0; h < HH; h++) {
        const int bh = b * HH + h;
        __syncthreads();
        sts64(Qs, qreg, tid);
        sts64(Ks, kreg, tid);
        __syncthreads();

        float acc[4][4][4];
#pragma unroll
        for (int i = 0; i < 4; i++)
#pragma unroll
            for (int j = 0; j < 4; j++)
#pragma unroll
                for (int c = 0; c < 4; c++) acc[i][j][c] = 0.0f;
        qk_mma(acc, Qs, Ks, wmq, wnq, gid, tig);

        if (h + 1 < HH) {
            const int bh2 = bh + 1;
            load64_regs(qreg, g_q + ((size_t)bh2 * TT + qt * 128) * HD, tid);
            load64_regs(kreg, g_k + ((size_t)bh2 * TT + kt * 128) * HD, tid);
        }

        float rz[4][2];
#pragma unroll
        for (int i = 0; i < 4; i++) {
            const size_t zb = (size_t)bh * TT + qt * 128 + wmq + i * 16 + gid;
            rz[i][0] = 0.125f / g_Z[zb];
            rz[i][1] = 0.125f / g_Z[zb + 8];
        }
#pragma unroll
        for (int i = 0; i < 4; i++)
#pragma unroll
            for (int j = 0; j < 4; j++)
#pragma unroll
                for (int c = 0; c < 4; c++)
                    aacc[i][j][c] += __expf(acc[i][j][c]) * rz[i][c >> 1];
    }

#pragma unroll
    for (int i = 0; i < 4; i++)
#pragma unroll
        for (int c2 = 0; c2 < 2; c2++) {
            const int row = qt * 128 + wmq + i * 16 + gid + c2 * 8;
#pragma unroll
            for (int j = 0; j < 4; j++) {
                const int col = kt * 128 + wnq + j * 8 + 2 * tig;
                float2 v = make_float2(aacc[i][j][c2 * 2], aacc[i][j][c2 * 2 + 1]);
                *reinterpret_cast<float2*>(
                    &avg_out[((size_t)b * TT + row) * TT + col]) = v;
            }
        }
}

// ===========================================================================
// tf32 GEMM for QKV in-projection (EPI 0) and out-projection (EPI 3).
// Unchanged (validated rounds 4-7).
// ===========================================================================
__device__ __forceinline__ int kperm(int k) {
    const int g = k >> 3, kk = k & 7;
    return g * 8 + ((kk & 3) * 2 + (kk >> 2));
}

template<int EPI, int BM, int BN, int WM, int WN, int K, int LDA, int LDB>
__global__ __launch_bounds__(256)
void mma_gemm(const float* __restrict__ Aext, const float* __restrict__ Bext,
              const float* __restrict__ bias, float* __restrict__ Cext)
{
    constexpr int BK = 16;
    constexpr int WARPS_N = BN / WN;
    constexpr int MT = WM / 16;
    constexpr int NT = WN / 8;
    static_assert((BM / WM) * (BN / WN) == 8, "8 warps");

    const int tid  = threadIdx.x;
    const int lane = tid & 31;
    const int warp = tid >> 5;
    const int wm0  = (warp / WARPS_N) * WM;
    const int wn0  = (warp % WARPS_N) * WN;
    const int m0   = blockIdx.y * BM;
    const int n0   = blockIdx.x * BN;

    const float* A  = (EPI == 0) ? Aext : g_mid;
    const float* Bm = Bext;

    __shared__ __align__(16) uint32_t As[2][BM][SPAD];
    __shared__ __align__(16) uint32_t Bs[2][BN][SPAD];

    float acc[MT][NT][4];
#pragma unroll
    for (int i = 0; i < MT; i++)
#pragma unroll
        for (int j = 0; j < NT; j++)
#pragma unroll
            for (int c = 0; c < 4; c++) acc[i][j][c] = 0.0f;

    const int lrow = tid >> 2;
    const int lcol = (tid & 3) << 2;
    const int c0 = kperm(lcol), c1 = kperm(lcol + 1),
              c2 = kperm(lcol + 2), c3 = kperm(lcol + 3);

    const int gid = lane >> 2;
    const int tig = lane & 3;

#pragma unroll
    for (int r = lrow; r < BM; r += 64) {
        float4 v = *reinterpret_cast<const float4*>(&A[(size_t)(m0 + r) * LDA + lcol]);
        As[0][r][c0] = to_tf32(v.x); As[0][r][c1] = to_tf32(v.y);
        As[0][r][c2] = to_tf32(v.z); As[0][r][c3] = to_tf32(v.w);
    }
#pragma unroll
    for (int r = lrow; r < BN; r += 64) {
        float4 v = *reinterpret_cast<const float4*>(&Bm[(size_t)(n0 + r) * LDB + lcol]);
        Bs[0][r][c0] = to_tf32(v.x); Bs[0][r][c1] = to_tf32(v.y);
        Bs[0][r][c2] = to_tf32(v.z); Bs[0][r][c3] = to_tf32(v.w);
    }
    __syncthreads();

    int buf = 0;

#pragma unroll 1
    for (int k0 = 0; k0 < K; k0 += BK) {
        const bool has_next = (k0 + BK) < K;
        float4 pa[BM / 64], pb[(BN + 63) / 64];
        if (has_next) {
#pragma unroll
            for (int q = 0; q < BM / 64; q++)
                pa[q] = *reinterpret_cast<const float4*>(
                    &A[(size_t)(m0 + lrow + q * 64) * LDA + k0 + BK + lcol]);
#pragma unroll
            for (int q = 0; q < (BN + 63) / 64; q++)
                if (lrow + q * 64 < BN)
                    pb[q] = *reinterpret_cast<const float4*>(
                        &Bm[(size_t)(n0 + lrow + q * 64) * LDB + k0 + BK + lcol]);
        }

#pragma unroll
        for (int g = 0; g < 2; g++) {
            const int kc = g * 8 + 2 * tig;
            uint2 alo[MT], ahi[MT], bfr[NT];
#pragma unroll
            for (int i = 0; i < MT; i++) {
                const int row = wm0 + i * 16 + gid;
                alo[i] = *reinterpret_cast<const uint2*>(&As[buf][row][kc]);
                ahi[i] = *reinterpret_cast<const uint2*>(&As[buf][row + 8][kc]);
            }
#pragma unroll
            for (int j = 0; j < NT; j++)
                bfr[j] = *reinterpret_cast<const uint2*>(&Bs[buf][wn0 + j * 8 + gid][kc]);
#pragma unroll
            for (int i = 0; i < MT; i++)
#pragma unroll
                for (int j = 0; j < NT; j++)
                    MMA_TF32(acc[i][j], alo[i].x, ahi[i].x, alo[i].y, ahi[i].y,
                             bfr[j].x, bfr[j].y);
        }

        if (has_next) {
            const int nb = buf ^ 1;
#pragma unroll
            for (int q = 0; q < BM / 64; q++) {
                const int r = lrow + q * 64;
                As[nb][r][c0] = to_tf32(pa[q].x); As[nb][r][c1] = to_tf32(pa[q].y);
                As[nb][r][c2] = to_tf32(pa[q].z); As[nb][r][c3] = to_tf32(pa[q].w);
            }
#pragma unroll
            for (int q = 0; q < (BN + 63) / 64; q++) {
                const int r = lrow + q * 64;
                if (r < BN) {
                    Bs[nb][r][c0] = to_tf32(pb[q].x); Bs[nb][r][c1] = to_tf32(pb[q].y);
                    Bs[nb][r][c2] = to_tf32(pb[q].z); Bs[nb][r][c3] = to_tf32(pb[q].w);
                }
            }
            __syncthreads();
            buf = nb;
        }
    }

    // Epilogue
#pragma unroll
    for (int i = 0; i < MT; i++) {
        const int rbase = m0 + wm0 + i * 16 + gid;
#pragma unroll
        for (int j = 0; j < NT; j++) {
            const int cbase = n0 + wn0 + j * 8 + tig * 2;
#pragma unroll
            for (int c = 0; c < 4; c++) {
                const int m = rbase + (c >> 1) * 8;
                const int n = cbase + (c & 1);
                float v = acc[i][j][c] + bias[n];
                if constexpr (EPI == 0) {
                    const int t = m >> 2, b = m & 3;
                    const int sec = n >> 9, h = (n >> 6) & 7, d = n & 63;
                    const int bh = b * HH + h;
                    if (sec == 0)
                        g_q[((size_t)bh * TT + t) * HD + d] = v * SCALE;
                    else if (sec == 1)
                        g_k[((size_t)bh * TT + t) * HD + d] = v;
                    else
                        g_vt[((size_t)bh * HD + d) * TT + t] = v;
                } else {
                    Cext[(size_t)m * EE + n] = v;
                }
            }
        }
    }
}

// ---------------------------------------------------------------------------
extern "C" void kernel_launch(void* const* d_in, const int* in_sizes, int n_in,
                              void* d_out, int out_size)
{
    const float* x     = (const float*)d_in[0];  // [T,B,E]
    const float* w_in  = (const float*)d_in[1];  // [3E,E]
    const float* b_in  = (const float*)d_in[2];  // [3E]
    const float* w_out = (const float*)d_in[3];  // [E,E]
    const float* b_out = (const float*)d_in[4];  // [E]

    float* out      = (float*)d_out;
    float* attn_out = out;                              // T*B*E
    float* avg_out  = out + (size_t)TT * BB * EE;       // B*T*T

    cudaFuncSetAttribute(fused_attn, cudaFuncAttributeMaxDynamicSharedMemorySize,
                         FUSED_SMEM);
    cudaFuncSetAttribute(avg_attn, cudaFuncAttributeMaxDynamicSharedMemorySize,
                         AVG_SMEM);

    // 1) QKV in-projection: [8192,512] x [1536,512]^T
    {
        dim3 grid(3 * EE / 128, (TT * BB) / 128, 1);
        mma_gemm<0, 128, 128, 64, 32, EE, EE, EE><<<grid, 256>>>(x, w_in, b_in, nullptr);
    }
    // 2) Fused attention: scores + exp + rowsum + PV, per (q-tile, head)
    {
        dim3 grid(TT / 128, BH, 1);
        fused_attn<<<grid, 256, FUSED_SMEM>>>();
    }
    // 3) avg_weights recompute pass
    {
        dim3 grid(TT / 128, TT / 128, BB);
        avg_attn<<<grid, 256, AVG_SMEM>>>(avg_out);
    }
    // 4) Out projection: [8192,512] x [512,512]^T -> d_out
    {
        dim3 grid(EE / 128, (TT * BB) / 128, 1);
        mma_gemm<3, 128, 128, 64, 32, EE, EE, EE><<<grid, 256>>>(nullptr, w_out, b_out, attn_out);
    }
}

// round 9
// speedup vs baseline: 2.9508x; 1.2180x over previous
#include <cuda_runtime.h>
#include <cuda_fp16.h>
#include <cstdint>
#include <cstddef>

// Problem constants
#define TT   2048
#define BB   4
#define EE   512
#define HH   8
#define HD   64
#define BH   32            // B*H
#define SCALE 0.125f       // HD^-0.5
#define SPAD 18            // smem row pad for mma_gemm (validated round 4)

// Scratch (static device allocations; no cudaMalloc allowed).
__device__ __align__(16) float g_q [(size_t)BH * TT * HD];     // [bh][t][d], pre-scaled
__device__ __align__(16) float g_k [(size_t)BH * TT * HD];     // [bh][t][d]
__device__ __align__(16) float g_vt[(size_t)BH * HD * TT];     // [bh][d][t]  (V transposed)
__device__ __align__(16) float g_mid[(size_t)TT * BB * EE];    // attn pre-projection, [t][b][e]
__device__ __align__(16) float g_Z[(size_t)BH * TT];           // softmax denominators
__device__ __align__(16) __half g_p16[(size_t)BH * TT * TT];   // exp(S) in fp16, 256 MB

__device__ __forceinline__ uint32_t to_tf32(float f) {
    uint32_t r;
    asm("cvt.rna.tf32.f32 %0, %1;" : "=r"(r) : "f"(f));
    return r;
}

#define MMA_TF32(acc, a0, a1, a2, a3, b0, b1)                              \
    asm volatile(                                                          \
        "mma.sync.aligned.m16n8k8.row.col.f32.tf32.tf32.f32 "              \
        "{%0,%1,%2,%3}, {%4,%5,%6,%7}, {%8,%9}, {%0,%1,%2,%3};\n"          \
        : "+f"((acc)[0]), "+f"((acc)[1]), "+f"((acc)[2]), "+f"((acc)[3])   \
        : "r"(a0), "r"(a1), "r"(a2), "r"(a3), "r"(b0), "r"(b1))

// ===========================================================================
// smem layout constants (words = uint32). Row strides: stride/2 mod 16 == 4
// -> fragment LDS.64 bank-conflict-free.
// ===========================================================================
constexpr int QS_W = 72;                       // stride for 64-wide k tiles
constexpr int PS_W = 136;                      // stride for 128-wide k tiles
constexpr int FUSED_SMEM = (128 * QS_W + 64 * PS_W) * 4;   // K + V^T = 71680 B

// ---------------------------------------------------------------------------
// Staging: gmem->reg and reg->smem (tf32 + k8-group permutation).
// Permutation: logical k -> g*8 + ((k&3)*2 + ((k&7)>>2)); float4 at c4 lands
// at (c4&~7)+((c4>>2)&1) + {0,2,4,6}.
// ---------------------------------------------------------------------------
__device__ __forceinline__ void load64_regs(float4 r[8], const float* __restrict__ src,
                                            int tid)
{
#pragma unroll
    for (int rr = 0; rr < 2; rr++) {
        const int row = (tid >> 2) + rr * 64;
#pragma unroll
        for (int cc = 0; cc < 4; cc++) {
            const int c4 = ((tid & 3) + cc * 4) << 2;
            r[rr * 4 + cc] = *reinterpret_cast<const float4*>(src + row * HD + c4);
        }
    }
}
__device__ __forceinline__ void sts64(uint32_t* __restrict__ dst, const float4 r[8],
                                      int tid)
{
#pragma unroll
    for (int rr = 0; rr < 2; rr++) {
        const int row = (tid >> 2) + rr * 64;
        uint32_t* d = dst + row * QS_W;
#pragma unroll
        for (int cc = 0; cc < 4; cc++) {
            const int c4 = ((tid & 3) + cc * 4) << 2;
            uint32_t* p = d + (c4 & ~7) + ((c4 >> 2) & 1);
            const float4 v = r[rr * 4 + cc];
            p[0] = to_tf32(v.x); p[2] = to_tf32(v.y);
            p[4] = to_tf32(v.z); p[6] = to_tf32(v.w);
        }
    }
}
// V^T tile: 64 rows (d) x 128 cols (t), src row stride TT.
__device__ __forceinline__ void loadv_regs(float4 r[8], const float* __restrict__ src,
                                           int tid)
{
#pragma unroll
    for (int rr = 0; rr < 2; rr++) {
        const int d = (tid >> 3) + rr * 32;
#pragma unroll
        for (int cc = 0; cc < 4; cc++) {
            const int c4 = ((tid & 7) + cc * 8) << 2;
            r[rr * 4 + cc] = *reinterpret_cast<const float4*>(src + (size_t)d * TT + c4);
        }
    }
}
__device__ __forceinline__ void stsv(uint32_t* __restrict__ dst, const float4 r[8],
                                     int tid)
{
#pragma unroll
    for (int rr = 0; rr < 2; rr++) {
        const int d = (tid >> 3) + rr * 32;
        uint32_t* dd = dst + d * PS_W;
#pragma unroll
        for (int cc = 0; cc < 4; cc++) {
            const int c4 = ((tid & 7) + cc * 8) << 2;
            uint32_t* p = dd + (c4 & ~7) + ((c4 >> 2) & 1);
            const float4 v = r[rr * 4 + cc];
            p[0] = to_tf32(v.x); p[2] = to_tf32(v.y);
            p[4] = to_tf32(v.z); p[6] = to_tf32(v.w);
        }
    }
}

// ===========================================================================
// Fused attention v2 (validated round 8) + fp16 expS side-store.
// One block per (bh, q-tile of 128), 8 warps, each warp owns 16 q-rows.
// ===========================================================================
__global__ __launch_bounds__(256, 2)
void fused_attn()
{
    extern __shared__ uint32_t sm[];
    uint32_t* Ks = sm;                    // [128][QS_W]
    uint32_t* Vs = sm + 128 * QS_W;       // [64][PS_W]

    const int qt = blockIdx.x, bh = blockIdx.y;
    const int tid = threadIdx.x, lane = tid & 31, warp = tid >> 5;
    const int gid = lane >> 2, tig = lane & 3;
    const int r0 = warp * 16 + gid;       // this lane's low row within tile

    // ---- stage Q once through the Ks buffer, pull A-fragments to regs ----
    uint32_t qa[8][4];
    {
        float4 q[8];
        load64_regs(q, g_q + ((size_t)bh * TT + qt * 128) * HD, tid);
        sts64(Ks, q, tid);
        __syncthreads();
#pragma unroll
        for (int g = 0; g < 8; g++) {
            const int kc = g * 8 + 2 * tig;
            uint2 lo = *reinterpret_cast<const uint2*>(Ks + r0 * QS_W + kc);
            uint2 hi = *reinterpret_cast<const uint2*>(Ks + (r0 + 8) * QS_W + kc);
            qa[g][0] = lo.x; qa[g][1] = hi.x; qa[g][2] = lo.y; qa[g][3] = hi.y;
        }
        __syncthreads();
    }

    float oacc[8][4];
#pragma unroll
    for (int j = 0; j < 8; j++)
#pragma unroll
        for (int c = 0; c < 4; c++) oacc[j][c] = 0.0f;
    float zr0 = 0.0f, zr1 = 0.0f;

    const float* Kbase = g_k + (size_t)bh * TT * HD;
    const float* Vbase = g_vt + (size_t)bh * HD * TT;
    // p16 row bases for this lane's two rows
    __half* p16r0 = g_p16 + ((size_t)bh * TT + qt * 128 + r0) * TT;
    __half* p16r1 = p16r0 + (size_t)8 * TT;

#pragma unroll 1
    for (int kt = 0; kt < 16; kt++) {
        __syncthreads();   // prior iter's consumers done with Ks/Vs
        {
            float4 kr[8];
            load64_regs(kr, Kbase + (size_t)kt * 128 * HD, tid);
            sts64(Ks, kr, tid);
        }
        {
            float4 vr[8];
            loadv_regs(vr, Vbase + kt * 128, tid);
            stsv(Vs, vr, tid);
        }
        __syncthreads();

#pragma unroll 1
        for (int half = 0; half < 2; half++) {
            // ---- S half: rows [16w,16w+16), cols [64*half, 64*half+64) ----
            float acc[8][4];
#pragma unroll
            for (int jj = 0; jj < 8; jj++)
#pragma unroll
                for (int c = 0; c < 4; c++) acc[jj][c] = 0.0f;

#pragma unroll
            for (int g = 0; g < 8; g++) {
#pragma unroll
                for (int jj = 0; jj < 8; jj++) {
                    const int j = half * 8 + jj;
                    uint2 b = *reinterpret_cast<const uint2*>(
                        Ks + (8 * j + gid) * QS_W + 8 * g + 2 * tig);
                    MMA_TF32(acc[jj], qa[g][0], qa[g][1], qa[g][2], qa[g][3],
                             b.x, b.y);
                }
            }

            // ---- exp, Z, fp16 side-store, C-frag -> A-frag shuffle, PV mma ----
#pragma unroll
            for (int jj = 0; jj < 8; jj++) {
                const int g = half * 8 + jj;       // PV k-group = S n-tile
                const float e0 = __expf(acc[jj][0]);
                const float e1 = __expf(acc[jj][1]);
                const float e2 = __expf(acc[jj][2]);
                const float e3 = __expf(acc[jj][3]);
                zr0 += e0 + e1;
                zr1 += e2 + e3;

                // side-store exp(S) as fp16 for the avg pass
                {
                    const int colk = kt * 128 + half * 64 + jj * 8 + 2 * tig;
                    *reinterpret_cast<__half2*>(p16r0 + colk) =
                        __halves2half2(__float2half(e0), __float2half(e1));
                    *reinterpret_cast<__half2*>(p16r1 + colk) =
                        __halves2half2(__float2half(e2), __float2half(e3));
                }

                const int s0 = (lane & ~3) | (tig >> 1);
                const int s1 = s0 + 2;
                const float p00 = __shfl_sync(0xffffffffu, e0, s0);
                const float p01 = __shfl_sync(0xffffffffu, e1, s0);
                const float p10 = __shfl_sync(0xffffffffu, e2, s0);
                const float p11 = __shfl_sync(0xffffffffu, e3, s0);
                const float q00 = __shfl_sync(0xffffffffu, e0, s1);
                const float q01 = __shfl_sync(0xffffffffu, e1, s1);
                const float q10 = __shfl_sync(0xffffffffu, e2, s1);
                const float q11 = __shfl_sync(0xffffffffu, e3, s1);
                const bool odd = (tig & 1) != 0;
                const uint32_t a0 = to_tf32(odd ? p01 : p00);
                const uint32_t a1 = to_tf32(odd ? p11 : p10);
                const uint32_t a2 = to_tf32(odd ? q01 : q00);
                const uint32_t a3 = to_tf32(odd ? q11 : q10);

#pragma unroll
                for (int j2 = 0; j2 < 8; j2++) {
                    uint2 b = *reinterpret_cast<const uint2*>(
                        Vs + (8 * j2 + gid) * PS_W + 8 * g + 2 * tig);
                    MMA_TF32(oacc[j2], a0, a1, a2, a3, b.x, b.y);
                }
            }
        }
    }

    // ---- Z: reduce over quad (rows are warp-exclusive; no smem needed) ----
    zr0 += __shfl_xor_sync(0xffffffffu, zr0, 1);
    zr0 += __shfl_xor_sync(0xffffffffu, zr0, 2);
    zr1 += __shfl_xor_sync(0xffffffffu, zr1, 1);
    zr1 += __shfl_xor_sync(0xffffffffu, zr1, 2);
    if (tig == 0) {
        g_Z[(size_t)bh * TT + qt * 128 + r0]     = zr0;
        g_Z[(size_t)bh * TT + qt * 128 + r0 + 8] = zr1;
    }

    // ---- epilogue: O / Z -> g_mid [t][b][e] ----
    const int b = bh >> 3, h = bh & 7;
    const float rz0 = 1.0f / zr0;
    const float rz1 = 1.0f / zr1;
#pragma unroll
    for (int j2 = 0; j2 < 8; j2++) {
        const int d = h * HD + j2 * 8 + 2 * tig;
        const int t0 = qt * 128 + r0;
        float2 v0 = make_float2(oacc[j2][0] * rz0, oacc[j2][1] * rz0);
        float2 v1 = make_float2(oacc[j2][2] * rz1, oacc[j2][3] * rz1);
        *reinterpret_cast<float2*>(&g_mid[((size_t)t0 * BB + b) * EE + d])       = v0;
        *reinterpret_cast<float2*>(&g_mid[((size_t)(t0 + 8) * BB + b) * EE + d]) = v1;
    }
}

// ===========================================================================
// avg pass: pure memory-bound scale-and-sum over stored fp16 exp(S).
// One block per (q, b); 256 threads x 8 k-values each.
// avg[b][q][k] = sum_h p16[bh][q][k] * (0.125 / Z[bh][q])
// ===========================================================================
__global__ __launch_bounds__(256)
void avg_scale(float* __restrict__ avg_out)
{
    const int q = blockIdx.x, b = blockIdx.y;
    const int tid = threadIdx.x;
    const int k0 = tid * 8;

    float acc[8];
#pragma unroll
    for (int i = 0; i < 8; i++) acc[i] = 0.0f;

#pragma unroll
    for (int h = 0; h < HH; h++) {
        const int bh = b * HH + h;
        const float rz = 0.125f / g_Z[(size_t)bh * TT + q];
        const uint4 raw = *reinterpret_cast<const uint4*>(
            g_p16 + ((size_t)bh * TT + q) * TT + k0);
        const __half2* hp = reinterpret_cast<const __half2*>(&raw);
#pragma unroll
        for (int i = 0; i < 4; i++) {
            const float2 f = __half22float2(hp[i]);
            acc[2 * i]     += f.x * rz;
            acc[2 * i + 1] += f.y * rz;
        }
    }

    float* dst = avg_out + ((size_t)b * TT + q) * TT + k0;
    *reinterpret_cast<float4*>(dst)     = make_float4(acc[0], acc[1], acc[2], acc[3]);
    *reinterpret_cast<float4*>(dst + 4) = make_float4(acc[4], acc[5], acc[6], acc[7]);
}

// ===========================================================================
// tf32 GEMM for QKV in-projection (EPI 0) and out-projection (EPI 3).
// Unchanged (validated rounds 4-8).
// ===========================================================================
__device__ __forceinline__ int kperm(int k) {
    const int g = k >> 3, kk = k & 7;
    return g * 8 + ((kk & 3) * 2 + (kk >> 2));
}

template<int EPI, int BM, int BN, int WM, int WN, int K, int LDA, int LDB>
__global__ __launch_bounds__(256)
void mma_gemm(const float* __restrict__ Aext, const float* __restrict__ Bext,
              const float* __restrict__ bias, float* __restrict__ Cext)
{
    constexpr int BK = 16;
    constexpr int WARPS_N = BN / WN;
    constexpr int MT = WM / 16;
    constexpr int NT = WN / 8;
    static_assert((BM / WM) * (BN / WN) == 8, "8 warps");

    const int tid  = threadIdx.x;
    const int lane = tid & 31;
    const int warp = tid >> 5;
    const int wm0  = (warp / WARPS_N) * WM;
    const int wn0  = (warp % WARPS_N) * WN;
    const int m0   = blockIdx.y * BM;
    const int n0   = blockIdx.x * BN;

    const float* A  = (EPI == 0) ? Aext : g_mid;
    const float* Bm = Bext;

    __shared__ __align__(16) uint32_t As[2][BM][SPAD];
    __shared__ __align__(16) uint32_t Bs[2][BN][SPAD];

    float acc[MT][NT][4];
#pragma unroll
    for (int i = 0; i < MT; i++)
#pragma unroll
        for (int j = 0; j < NT; j++)
#pragma unroll
            for (int c = 0; c < 4; c++) acc[i][j][c] = 0.0f;

    const int lrow = tid >> 2;
    const int lcol = (tid & 3) << 2;
    const int c0 = kperm(lcol), c1 = kperm(lcol + 1),
              c2 = kperm(lcol + 2), c3 = kperm(lcol + 3);

    const int gid = lane >> 2;
    const int tig = lane & 3;

#pragma unroll
    for (int r = lrow; r < BM; r += 64) {
        float4 v = *reinterpret_cast<const float4*>(&A[(size_t)(m0 + r) * LDA + lcol]);
        As[0][r][c0] = to_tf32(v.x); As[0][r][c1] = to_tf32(v.y);
        As[0][r][c2] = to_tf32(v.z); As[0][r][c3] = to_tf32(v.w);
    }
#pragma unroll
    for (int r = lrow; r < BN; r += 64) {
        float4 v = *reinterpret_cast<const float4*>(&Bm[(size_t)(n0 + r) * LDB + lcol]);
        Bs[0][r][c0] = to_tf32(v.x); Bs[0][r][c1] = to_tf32(v.y);
        Bs[0][r][c2] = to_tf32(v.z); Bs[0][r][c3] = to_tf32(v.w);
    }
    __syncthreads();

    int buf = 0;

#pragma unroll 1
    for (int k0 = 0; k0 < K; k0 += BK) {
        const bool has_next = (k0 + BK) < K;
        float4 pa[BM / 64], pb[(BN + 63) / 64];
        if (has_next) {
#pragma unroll
            for (int q = 0; q < BM / 64; q++)
                pa[q] = *reinterpret_cast<const float4*>(
                    &A[(size_t)(m0 + lrow + q * 64) * LDA + k0 + BK + lcol]);
#pragma unroll
            for (int q = 0; q < (BN + 63) / 64; q++)
                if (lrow + q * 64 < BN)
                    pb[q] = *reinterpret_cast<const float4*>(
                        &Bm[(size_t)(n0 + lrow + q * 64) * LDB + k0 + BK + lcol]);
        }

#pragma unroll
        for (int g = 0; g < 2; g++) {
            const int kc = g * 8 + 2 * tig;
            uint2 alo[MT], ahi[MT], bfr[NT];
#pragma unroll
            for (int i = 0; i < MT; i++) {
                const int row = wm0 + i * 16 + gid;
                alo[i] = *reinterpret_cast<const uint2*>(&As[buf][row][kc]);
                ahi[i] = *reinterpret_cast<const uint2*>(&As[buf][row + 8][kc]);
            }
#pragma unroll
            for (int j = 0; j < NT; j++)
                bfr[j] = *reinterpret_cast<const uint2*>(&Bs[buf][wn0 + j * 8 + gid][kc]);
#pragma unroll
            for (int i = 0; i < MT; i++)
#pragma unroll
                for (int j = 0; j < NT; j++)
                    MMA_TF32(acc[i][j], alo[i].x, ahi[i].x, alo[i].y, ahi[i].y,
                             bfr[j].x, bfr[j].y);
        }

        if (has_next) {
            const int nb = buf ^ 1;
#pragma unroll
            for (int q = 0; q < BM / 64; q++) {
                const int r = lrow + q * 64;
                As[nb][r][c0] = to_tf32(pa[q].x); As[nb][r][c1] = to_tf32(pa[q].y);
                As[nb][r][c2] = to_tf32(pa[q].z); As[nb][r][c3] = to_tf32(pa[q].w);
            }
#pragma unroll
            for (int q = 0; q < (BN + 63) / 64; q++) {
                const int r = lrow + q * 64;
                if (r < BN) {
                    Bs[nb][r][c0] = to_tf32(pb[q].x); Bs[nb][r][c1] = to_tf32(pb[q].y);
                    Bs[nb][r][c2] = to_tf32(pb[q].z); Bs[nb][r][c3] = to_tf32(pb[q].w);
                }
            }
            __syncthreads();
            buf = nb;
        }
    }

    // Epilogue
#pragma unroll
    for (int i = 0; i < MT; i++) {
        const int rbase = m0 + wm0 + i * 16 + gid;
#pragma unroll
        for (int j = 0; j < NT; j++) {
            const int cbase = n0 + wn0 + j * 8 + tig * 2;
#pragma unroll
            for (int c = 0; c < 4; c++) {
                const int m = rbase + (c >> 1) * 8;
                const int n = cbase + (c & 1);
                float v = acc[i][j][c] + bias[n];
                if constexpr (EPI == 0) {
                    const int t = m >> 2, b = m & 3;
                    const int sec = n >> 9, h = (n >> 6) & 7, d = n & 63;
                    const int bh = b * HH + h;
                    if (sec == 0)
                        g_q[((size_t)bh * TT + t) * HD + d] = v * SCALE;
                    else if (sec == 1)
                        g_k[((size_t)bh * TT + t) * HD + d] = v;
                    else
                        g_vt[((size_t)bh * HD + d) * TT + t] = v;
                } else {
                    Cext[(size_t)m * EE + n] = v;
                }
            }
        }
    }
}

// ---------------------------------------------------------------------------
extern "C" void kernel_launch(void* const* d_in, const int* in_sizes, int n_in,
                              void* d_out, int out_size)
{
    const float* x     = (const float*)d_in[0];  // [T,B,E]
    const float* w_in  = (const float*)d_in[1];  // [3E,E]
    const float* b_in  = (const float*)d_in[2];  // [3E]
    const float* w_out = (const float*)d_in[3];  // [E,E]
    const float* b_out = (const float*)d_in[4];  // [E]

    float* out      = (float*)d_out;
    float* attn_out = out;                              // T*B*E
    float* avg_out  = out + (size_t)TT * BB * EE;       // B*T*T

    cudaFuncSetAttribute(fused_attn, cudaFuncAttributeMaxDynamicSharedMemorySize,
                         FUSED_SMEM);

    // 1) QKV in-projection: [8192,512] x [1536,512]^T
    {
        dim3 grid(3 * EE / 128, (TT * BB) / 128, 1);
        mma_gemm<0, 128, 128, 64, 32, EE, EE, EE><<<grid, 256>>>(x, w_in, b_in, nullptr);
    }
    // 2) Fused attention: scores + exp + rowsum + PV (+ fp16 expS store)
    {
        dim3 grid(TT / 128, BH, 1);
        fused_attn<<<grid, 256, FUSED_SMEM>>>();
    }
    // 3) avg_weights: memory-bound scale-and-sum over fp16 expS
    {
        dim3 grid(TT, BB, 1);
        avg_scale<<<grid, 256>>>(avg_out);
    }
    // 4) Out projection: [8192,512] x [512,512]^T -> d_out
    {
        dim3 grid(EE / 128, (TT * BB) / 128, 1);
        mma_gemm<3, 128, 128, 64, 32, EE, EE, EE><<<grid, 256>>>(nullptr, w_out, b_out, attn_out);
    }
}

// round 11
// speedup vs baseline: 3.8987x; 1.3212x over previous
#include <cuda_runtime.h>
#include <cuda_fp16.h>
#include <cstdint>
#include <cstddef>
#include <cstring>

// Problem constants
#define TT   2048
#define BB   4
#define EE   512
#define HH   8
#define HD   64
#define BH   32            // B*H
#define SCALE 0.125f       // HD^-0.5
#define SPAD 18            // smem row pad for mma_gemm (validated round 4)

// Scratch (static device allocations; no cudaMalloc allowed).
__device__ __align__(16) float g_q [(size_t)BH * TT * HD];     // [bh][t][d], pre-scaled
__device__ __align__(16) float g_k [(size_t)BH * TT * HD];     // [bh][t][d]
__device__ __align__(16) float g_vt[(size_t)BH * HD * TT];     // [bh][d][t]  (V transposed)
__device__ __align__(16) float g_mid[(size_t)TT * BB * EE];    // attn pre-projection, [t][b][e]
__device__ __align__(16) float g_Z[(size_t)BH * TT];           // softmax denominators
__device__ __align__(16) __half g_p16[(size_t)BH * TT * TT];   // exp(S) in fp16, 256 MB

__device__ __forceinline__ uint32_t to_tf32(float f) {
    uint32_t r;
    asm("cvt.rna.tf32.f32 %0, %1;" : "=r"(r) : "f"(f));
    return r;
}
__device__ __forceinline__ uint32_t pack_h2(float lo, float hi) {
    __half2 h = __floats2half2_rn(lo, hi);
    uint32_t u;
    memcpy(&u, &h, 4);
    return u;
}

#define MMA_TF32(acc, a0, a1, a2, a3, b0, b1)                              \
    asm volatile(                                                          \
        "mma.sync.aligned.m16n8k8.row.col.f32.tf32.tf32.f32 "              \
        "{%0,%1,%2,%3}, {%4,%5,%6,%7}, {%8,%9}, {%0,%1,%2,%3};\n"          \
        : "+f"((acc)[0]), "+f"((acc)[1]), "+f"((acc)[2]), "+f"((acc)[3])   \
        : "r"(a0), "r"(a1), "r"(a2), "r"(a3), "r"(b0), "r"(b1))

#define MMA_F16(acc, a0, a1, a2, a3, b0, b1)                               \
    asm volatile(                                                          \
        "mma.sync.aligned.m16n8k16.row.col.f32.f16.f16.f32 "               \
        "{%0,%1,%2,%3}, {%4,%5,%6,%7}, {%8,%9}, {%0,%1,%2,%3};\n"          \
        : "+f"((acc)[0]), "+f"((acc)[1]), "+f"((acc)[2]), "+f"((acc)[3])   \
        : "r"(a0), "r"(a1), "r"(a2), "r"(a3), "r"(b0), "r"(b1))

// ===========================================================================
// Fused-attention smem (half2 words). Strides: W/2 mod 16 == 4 -> LDS.64
// bank-conflict-free (pair index = 4*gid + tig, distinct per 16-lane phase).
// ===========================================================================
constexpr int KS_W = 40;   // K/Q rows: 32 half2 data words + pad
constexpr int VS_W = 72;   // V^T rows: 64 half2 data words + pad
constexpr int FUSED_SMEM = (128 * KS_W + 64 * VS_W) * 4;   // 38912 B

// fp32-path stride (mma_gemm, validated)
constexpr int QS_W = 72;

// ---------------------------------------------------------------------------
// gmem->reg loaders (fp32 float4) — same coverage as rounds 7-9.
// ---------------------------------------------------------------------------
__device__ __forceinline__ void load64_regs(float4 r[8], const float* __restrict__ src,
                                            int tid)
{
#pragma unroll
    for (int rr = 0; rr < 2; rr++) {
        const int row = (tid >> 2) + rr * 64;
#pragma unroll
        for (int cc = 0; cc < 4; cc++) {
            const int c4 = ((tid & 3) + cc * 4) << 2;
            r[rr * 4 + cc] = *reinterpret_cast<const float4*>(src + row * HD + c4);
        }
    }
}
__device__ __forceinline__ void loadv_regs(float4 r[8], const float* __restrict__ src,
                                           int tid)
{
#pragma unroll
    for (int rr = 0; rr < 2; rr++) {
        const int d = (tid >> 3) + rr * 32;
#pragma unroll
        for (int cc = 0; cc < 4; cc++) {
            const int c4 = ((tid & 7) + cc * 8) << 2;
            r[rr * 4 + cc] = *reinterpret_cast<const float4*>(src + (size_t)d * TT + c4);
        }
    }
}

// ---------------------------------------------------------------------------
// reg->smem fp16 stores with per-k16-group word permutation:
// word w -> g*8 + ((w&7)&3)*2 + ((w&7)>>2). A float4 (2 words, even w8) lands
// at permuted positions p0 and p0+2.
// ---------------------------------------------------------------------------
__device__ __forceinline__ void sts64h(uint32_t* __restrict__ dst, const float4 r[8],
                                       int tid)
{
#pragma unroll
    for (int rr = 0; rr < 2; rr++) {
        const int row = (tid >> 2) + rr * 64;
        uint32_t* d = dst + row * KS_W;
#pragma unroll
        for (int cc = 0; cc < 4; cc++) {
            const int c4 = ((tid & 3) + cc * 4) << 2;
            const int w = c4 >> 1, g = w >> 3, w8 = w & 7;
            const int p0 = (w8 & 3) * 2 + (w8 >> 2);
            const float4 v = r[rr * 4 + cc];
            d[g * 8 + p0]     = pack_h2(v.x, v.y);
            d[g * 8 + p0 + 2] = pack_h2(v.z, v.w);
        }
    }
}
__device__ __forceinline__ void stsvh(uint32_t* __restrict__ dst, const float4 r[8],
                                      int tid)
{
#pragma unroll
    for (int rr = 0; rr < 2; rr++) {
        const int dd = (tid >> 3) + rr * 32;
        uint32_t* dr = dst + dd * VS_W;
#pragma unroll
        for (int cc = 0; cc < 4; cc++) {
            const int c4 = ((tid & 7) + cc * 8) << 2;
            const int w = c4 >> 1, g = w >> 3, w8 = w & 7;
            const int p0 = (w8 & 3) * 2 + (w8 >> 2);
            const float4 v = r[rr * 4 + cc];
            dr[g * 8 + p0]     = pack_h2(v.x, v.y);
            dr[g * 8 + p0 + 2] = pack_h2(v.z, v.w);
        }
    }
}

// ===========================================================================
// Fused attention v3: fp16 m16n8k16. One block per (bh, q-tile of 128),
// 8 warps, each warp owns 16 q-rows. The QK C-fragment layout IS the PV
// A-fragment layout in fp16 -> zero shuffles.
// ===========================================================================
__global__ __launch_bounds__(256, 2)
void fused_attn()
{
    extern __shared__ uint32_t sm[];
    uint32_t* Ks = sm;                    // [128][KS_W]  (half2 words)
    uint32_t* Vs = sm + 128 * KS_W;       // [64][VS_W]

    const int qt = blockIdx.x, bh = blockIdx.y;
    const int tid = threadIdx.x, lane = tid & 31, warp = tid >> 5;
    const int gid = lane >> 2, tig = lane & 3;
    const int r0 = warp * 16 + gid;       // this lane's low row within tile

    // ---- stage Q once through Ks buffer (fp16), pull A-fragments ----
    uint32_t qa[4][4];                    // 4 k16 groups x {a0,a1,a2,a3}
    {
        float4 q[8];
        load64_regs(q, g_q + ((size_t)bh * TT + qt * 128) * HD, tid);
        sts64h(Ks, q, tid);
        __syncthreads();
#pragma unroll
        for (int g = 0; g < 4; g++) {
            uint2 lo = *reinterpret_cast<const uint2*>(Ks + r0 * KS_W + 8 * g + 2 * tig);
            uint2 hi = *reinterpret_cast<const uint2*>(Ks + (r0 + 8) * KS_W + 8 * g + 2 * tig);
            qa[g][0] = lo.x; qa[g][1] = hi.x; qa[g][2] = lo.y; qa[g][3] = hi.y;
        }
        __syncthreads();
    }

    float oacc[8][4];
#pragma unroll
    for (int j = 0; j < 8; j++)
#pragma unroll
        for (int c = 0; c < 4; c++) oacc[j][c] = 0.0f;
    float zr0 = 0.0f, zr1 = 0.0f;

    const float* Kbase = g_k + (size_t)bh * TT * HD;
    const float* Vbase = g_vt + (size_t)bh * HD * TT;
    __half* p16r0 = g_p16 + ((size_t)bh * TT + qt * 128 + r0) * TT;
    __half* p16r1 = p16r0 + (size_t)8 * TT;

#pragma unroll 1
    for (int kt = 0; kt < 16; kt++) {
        __syncthreads();   // prior iter's consumers done with Ks/Vs
        {
            float4 kr[8];
            load64_regs(kr, Kbase + (size_t)kt * 128 * HD, tid);
            sts64h(Ks, kr, tid);
        }
        {
            float4 vr[8];
            loadv_regs(vr, Vbase + kt * 128, tid);
            stsvh(Vs, vr, tid);
        }
        __syncthreads();

#pragma unroll 1
        for (int half = 0; half < 2; half++) {
            // ---- S half: rows [16w,16w+16), cols [64*half, 64*half+64) ----
            float acc[8][4];
#pragma unroll
            for (int jj = 0; jj < 8; jj++)
#pragma unroll
                for (int c = 0; c < 4; c++) acc[jj][c] = 0.0f;

#pragma unroll
            for (int g = 0; g < 4; g++) {
#pragma unroll
                for (int jj = 0; jj < 8; jj++) {
                    const int j = half * 8 + jj;
                    uint2 b = *reinterpret_cast<const uint2*>(
                        Ks + (8 * j + gid) * KS_W + 8 * g + 2 * tig);
                    MMA_F16(acc[jj], qa[g][0], qa[g][1], qa[g][2], qa[g][3],
                            b.x, b.y);
                }
            }

            // ---- exp, Z, fp16 pack (+side-store) ----
            uint32_t ph01[8], ph23[8];
#pragma unroll
            for (int jj = 0; jj < 8; jj++) {
                const float e0 = __expf(acc[jj][0]);
                const float e1 = __expf(acc[jj][1]);
                const float e2 = __expf(acc[jj][2]);
                const float e3 = __expf(acc[jj][3]);
                zr0 += e0 + e1;
                zr1 += e2 + e3;
                ph01[jj] = pack_h2(e0, e1);
                ph23[jj] = pack_h2(e2, e3);
                const int colk = kt * 128 + half * 64 + jj * 8 + 2 * tig;
                *reinterpret_cast<uint32_t*>(p16r0 + colk) = ph01[jj];
                *reinterpret_cast<uint32_t*>(p16r1 + colk) = ph23[jj];
            }

            // ---- O += P V : C-frag == A-frag, groups 4*half..4*half+3 ----
#pragma unroll
            for (int gp = 0; gp < 4; gp++) {
                const int g = half * 4 + gp;
                const uint32_t a0 = ph01[2 * gp],     a1 = ph23[2 * gp];
                const uint32_t a2 = ph01[2 * gp + 1], a3 = ph23[2 * gp + 1];
#pragma unroll
                for (int j2 = 0; j2 < 8; j2++) {
                    uint2 b = *reinterpret_cast<const uint2*>(
                        Vs + (8 * j2 + gid) * VS_W + 8 * g + 2 * tig);
                    MMA_F16(oacc[j2], a0, a1, a2, a3, b.x, b.y);
                }
            }
        }
    }

    // ---- Z: reduce over quad ----
    zr0 += __shfl_xor_sync(0xffffffffu, zr0, 1);
    zr0 += __shfl_xor_sync(0xffffffffu, zr0, 2);
    zr1 += __shfl_xor_sync(0xffffffffu, zr1, 1);
    zr1 += __shfl_xor_sync(0xffffffffu, zr1, 2);
    if (tig == 0) {
        g_Z[(size_t)bh * TT + qt * 128 + r0]     = zr0;
        g_Z[(size_t)bh * TT + qt * 128 + r0 + 8] = zr1;
    }

    // ---- epilogue: O / Z -> g_mid [t][b][e] ----
    const int b = bh >> 3, h = bh & 7;
    const float rz0 = 1.0f / zr0;
    const float rz1 = 1.0f / zr1;
#pragma unroll
    for (int j2 = 0; j2 < 8; j2++) {
        const int d = h * HD + j2 * 8 + 2 * tig;
        const int t0 = qt * 128 + r0;
        float2 v0 = make_float2(oacc[j2][0] * rz0, oacc[j2][1] * rz0);
        float2 v1 = make_float2(oacc[j2][2] * rz1, oacc[j2][3] * rz1);
        *reinterpret_cast<float2*>(&g_mid[((size_t)t0 * BB + b) * EE + d])       = v0;
        *reinterpret_cast<float2*>(&g_mid[((size_t)(t0 + 8) * BB + b) * EE + d]) = v1;
    }
}

// ===========================================================================
// avg pass (validated round 9): memory-bound scale-and-sum over fp16 exp(S).
// ===========================================================================
__global__ __launch_bounds__(256)
void avg_scale(float* __restrict__ avg_out)
{
    const int q = blockIdx.x, b = blockIdx.y;
    const int tid = threadIdx.x;
    const int k0 = tid * 8;

    float acc[8];
#pragma unroll
    for (int i = 0; i < 8; i++) acc[i] = 0.0f;

#pragma unroll
    for (int h = 0; h < HH; h++) {
        const int bh = b * HH + h;
        const float rz = 0.125f / g_Z[(size_t)bh * TT + q];
        const uint4 raw = *reinterpret_cast<const uint4*>(
            g_p16 + ((size_t)bh * TT + q) * TT + k0);
        const __half2* hp = reinterpret_cast<const __half2*>(&raw);
#pragma unroll
        for (int i = 0; i < 4; i++) {
            const float2 f = __half22float2(hp[i]);
            acc[2 * i]     += f.x * rz;
            acc[2 * i + 1] += f.y * rz;
        }
    }

    float* dst = avg_out + ((size_t)b * TT + q) * TT + k0;
    *reinterpret_cast<float4*>(dst)     = make_float4(acc[0], acc[1], acc[2], acc[3]);
    *reinterpret_cast<float4*>(dst + 4) = make_float4(acc[4], acc[5], acc[6], acc[7]);
}

// ===========================================================================
// tf32 GEMM for QKV in-projection (EPI 0) and out-projection (EPI 3).
// Unchanged (validated rounds 4-9).
// ===========================================================================
__device__ __forceinline__ int kperm(int k) {
    const int g = k >> 3, kk = k & 7;
    return g * 8 + ((kk & 3) * 2 + (kk >> 2));
}

template<int EPI, int BM, int BN, int WM, int WN, int K, int LDA, int LDB>
__global__ __launch_bounds__(256)
void mma_gemm(const float* __restrict__ Aext, const float* __restrict__ Bext,
              const float* __restrict__ bias, float* __restrict__ Cext)
{
    constexpr int BK = 16;
    constexpr int WARPS_N = BN / WN;
    constexpr int MT = WM / 16;
    constexpr int NT = WN / 8;
    static_assert((BM / WM) * (BN / WN) == 8, "8 warps");

    const int tid  = threadIdx.x;
    const int lane = tid & 31;
    const int warp = tid >> 5;
    const int wm0  = (warp / WARPS_N) * WM;
    const int wn0  = (warp % WARPS_N) * WN;
    const int m0   = blockIdx.y * BM;
    const int n0   = blockIdx.x * BN;

    const float* A  = (EPI == 0) ? Aext : g_mid;
    const float* Bm = Bext;

    __shared__ __align__(16) uint32_t As[2][BM][SPAD];
    __shared__ __align__(16) uint32_t Bs[2][BN][SPAD];

    float acc[MT][NT][4];
#pragma unroll
    for (int i = 0; i < MT; i++)
#pragma unroll
        for (int j = 0; j < NT; j++)
#pragma unroll
            for (int c = 0; c < 4; c++) acc[i][j][c] = 0.0f;

    const int lrow = tid >> 2;
    const int lcol = (tid & 3) << 2;
    const int c0 = kperm(lcol), c1 = kperm(lcol + 1),
              c2 = kperm(lcol + 2), c3 = kperm(lcol + 3);

    const int gid = lane >> 2;
    const int tig = lane & 3;

#pragma unroll
    for (int r = lrow; r < BM; r += 64) {
        float4 v = *reinterpret_cast<const float4*>(&A[(size_t)(m0 + r) * LDA + lcol]);
        As[0][r][c0] = to_tf32(v.x); As[0][r][c1] = to_tf32(v.y);
        As[0][r][c2] = to_tf32(v.z); As[0][r][c3] = to_tf32(v.w);
    }
#pragma unroll
    for (int r = lrow; r < BN; r += 64) {
        float4 v = *reinterpret_cast<const float4*>(&Bm[(size_t)(n0 + r) * LDB + lcol]);
        Bs[0][r][c0] = to_tf32(v.x); Bs[0][r][c1] = to_tf32(v.y);
        Bs[0][r][c2] = to_tf32(v.z); Bs[0][r][c3] = to_tf32(v.w);
    }
    __syncthreads();

    int buf = 0;

#pragma unroll 1
    for (int k0 = 0; k0 < K; k0 += BK) {
        const bool has_next = (k0 + BK) < K;
        float4 pa[BM / 64], pb[(BN + 63) / 64];
        if (has_next) {
#pragma unroll
            for (int q = 0; q < BM / 64; q++)
                pa[q] = *reinterpret_cast<const float4*>(
                    &A[(size_t)(m0 + lrow + q * 64) * LDA + k0 + BK + lcol]);
#pragma unroll
            for (int q = 0; q < (BN + 63) / 64; q++)
                if (lrow + q * 64 < BN)
                    pb[q] = *reinterpret_cast<const float4*>(
                        &Bm[(size_t)(n0 + lrow + q * 64) * LDB + k0 + BK + lcol]);
        }

#pragma unroll
        for (int g = 0; g < 2; g++) {
            const int kc = g * 8 + 2 * tig;
            uint2 alo[MT], ahi[MT], bfr[NT];
#pragma unroll
            for (int i = 0; i < MT; i++) {
                const int row = wm0 + i * 16 + gid;
                alo[i] = *reinterpret_cast<const uint2*>(&As[buf][row][kc]);
                ahi[i] = *reinterpret_cast<const uint2*>(&As[buf][row + 8][kc]);
            }
#pragma unroll
            for (int j = 0; j < NT; j++)
                bfr[j] = *reinterpret_cast<const uint2*>(&Bs[buf][wn0 + j * 8 + gid][kc]);
#pragma unroll
            for (int i = 0; i < MT; i++)
#pragma unroll
                for (int j = 0; j < NT; j++)
                    MMA_TF32(acc[i][j], alo[i].x, ahi[i].x, alo[i].y, ahi[i].y,
                             bfr[j].x, bfr[j].y);
        }

        if (has_next) {
            const int nb = buf ^ 1;
#pragma unroll
            for (int q = 0; q < BM / 64; q++) {
                const int r = lrow + q * 64;
                As[nb][r][c0] = to_tf32(pa[q].x); As[nb][r][c1] = to_tf32(pa[q].y);
                As[nb][r][c2] = to_tf32(pa[q].z); As[nb][r][c3] = to_tf32(pa[q].w);
            }
#pragma unroll
            for (int q = 0; q < (BN + 63) / 64; q++) {
                const int r = lrow + q * 64;
                if (r < BN) {
                    Bs[nb][r][c0] = to_tf32(pb[q].x); Bs[nb][r][c1] = to_tf32(pb[q].y);
                    Bs[nb][r][c2] = to_tf32(pb[q].z); Bs[nb][r][c3] = to_tf32(pb[q].w);
                }
            }
            __syncthreads();
            buf = nb;
        }
    }

    // Epilogue
#pragma unroll
    for (int i = 0; i < MT; i++) {
        const int rbase = m0 + wm0 + i * 16 + gid;
#pragma unroll
        for (int j = 0; j < NT; j++) {
            const int cbase = n0 + wn0 + j * 8 + tig * 2;
#pragma unroll
            for (int c = 0; c < 4; c++) {
                const int m = rbase + (c >> 1) * 8;
                const int n = cbase + (c & 1);
                float v = acc[i][j][c] + bias[n];
                if constexpr (EPI == 0) {
                    const int t = m >> 2, b = m & 3;
                    const int sec = n >> 9, h = (n >> 6) & 7, d = n & 63;
                    const int bh = b * HH + h;
                    if (sec == 0)
                        g_q[((size_t)bh * TT + t) * HD + d] = v * SCALE;
                    else if (sec == 1)
                        g_k[((size_t)bh * TT + t) * HD + d] = v;
                    else
                        g_vt[((size_t)bh * HD + d) * TT + t] = v;
                } else {
                    Cext[(size_t)m * EE + n] = v;
                }
            }
        }
    }
}

// ---------------------------------------------------------------------------
extern "C" void kernel_launch(void* const* d_in, const int* in_sizes, int n_in,
                              void* d_out, int out_size)
{
    const float* x     = (const float*)d_in[0];  // [T,B,E]
    const float* w_in  = (const float*)d_in[1];  // [3E,E]
    const float* b_in  = (const float*)d_in[2];  // [3E]
    const float* w_out = (const float*)d_in[3];  // [E,E]
    const float* b_out = (const float*)d_in[4];  // [E]

    float* out      = (float*)d_out;
    float* attn_out = out;                              // T*B*E
    float* avg_out  = out + (size_t)TT * BB * EE;       // B*T*T

    cudaFuncSetAttribute(fused_attn, cudaFuncAttributeMaxDynamicSharedMemorySize,
                         FUSED_SMEM);

    // 1) QKV in-projection: [8192,512] x [1536,512]^T
    {
        dim3 grid(3 * EE / 128, (TT * BB) / 128, 1);
        mma_gemm<0, 128, 128, 64, 32, EE, EE, EE><<<grid, 256>>>(x, w_in, b_in, nullptr);
    }
    // 2) Fused attention (fp16 mma): scores + exp + rowsum + PV (+ fp16 expS)
    {
        dim3 grid(TT / 128, BH, 1);
        fused_attn<<<grid, 256, FUSED_SMEM>>>();
    }
    // 3) avg_weights: memory-bound scale-and-sum over fp16 expS
    {
        dim3 grid(TT, BB, 1);
        avg_scale<<<grid, 256>>>(avg_out);
    }
    // 4) Out projection: [8192,512] x [512,512]^T -> d_out
    {
        dim3 grid(EE / 128, (TT * BB) / 128, 1);
        mma_gemm<3, 128, 128, 64, 32, EE, EE, EE><<<grid, 256>>>(nullptr, w_out, b_out, attn_out);
    }
}

// round 12
// speedup vs baseline: 4.5725x; 1.1728x over previous
#include <cuda_runtime.h>
#include <cuda_fp16.h>
#include <cstdint>
#include <cstddef>
#include <cstring>

// Problem constants
#define TT   2048
#define BB   4
#define EE   512
#define HH   8
#define HD   64
#define BH   32            // B*H
#define SCALE 0.125f       // HD^-0.5

// Scratch (static device allocations; no cudaMalloc allowed).
__device__ __align__(16) float g_q [(size_t)BH * TT * HD];     // [bh][t][d], pre-scaled
__device__ __align__(16) float g_k [(size_t)BH * TT * HD];     // [bh][t][d]
__device__ __align__(16) float g_vt[(size_t)BH * HD * TT];     // [bh][d][t]  (V transposed)
__device__ __align__(16) float g_mid[(size_t)TT * BB * EE];    // attn pre-projection, [t][b][e]
__device__ __align__(16) float g_Z[(size_t)BH * TT];           // softmax denominators
__device__ __align__(16) __half g_p16[(size_t)BH * TT * TT];   // exp(S) in fp16, 256 MB

__device__ __forceinline__ uint32_t pack_h2(float lo, float hi) {
    __half2 h = __floats2half2_rn(lo, hi);
    uint32_t u;
    memcpy(&u, &h, 4);
    return u;
}

#define MMA_F16(acc, a0, a1, a2, a3, b0, b1)                               \
    asm volatile(                                                          \
        "mma.sync.aligned.m16n8k16.row.col.f32.f16.f16.f32 "               \
        "{%0,%1,%2,%3}, {%4,%5,%6,%7}, {%8,%9}, {%0,%1,%2,%3};\n"          \
        : "+f"((acc)[0]), "+f"((acc)[1]), "+f"((acc)[2]), "+f"((acc)[3])   \
        : "r"(a0), "r"(a1), "r"(a2), "r"(a3), "r"(b0), "r"(b1))

// ===========================================================================
// Fused-attention smem (half2 words). Strides: W/2 mod 16 == 4 -> LDS.64
// bank-conflict-free (pair index = 4*gid + tig, distinct per 16-lane phase).
// ===========================================================================
constexpr int KS_W = 40;   // K/Q rows: 32 half2 data words + pad
constexpr int VS_W = 72;   // V^T rows: 64 half2 data words + pad
constexpr int FUSED_SMEM = (128 * KS_W + 64 * VS_W) * 4;   // 38912 B

// ---------------------------------------------------------------------------
// gmem->reg loaders (fp32 float4) — validated rounds 7-11.
// ---------------------------------------------------------------------------
__device__ __forceinline__ void load64_regs(float4 r[8], const float* __restrict__ src,
                                            int tid)
{
#pragma unroll
    for (int rr = 0; rr < 2; rr++) {
        const int row = (tid >> 2) + rr * 64;
#pragma unroll
        for (int cc = 0; cc < 4; cc++) {
            const int c4 = ((tid & 3) + cc * 4) << 2;
            r[rr * 4 + cc] = *reinterpret_cast<const float4*>(src + row * HD + c4);
        }
    }
}
__device__ __forceinline__ void loadv_regs(float4 r[8], const float* __restrict__ src,
                                           int tid)
{
#pragma unroll
    for (int rr = 0; rr < 2; rr++) {
        const int d = (tid >> 3) + rr * 32;
#pragma unroll
        for (int cc = 0; cc < 4; cc++) {
            const int c4 = ((tid & 7) + cc * 8) << 2;
            r[rr * 4 + cc] = *reinterpret_cast<const float4*>(src + (size_t)d * TT + c4);
        }
    }
}

// ---------------------------------------------------------------------------
// reg->smem fp16 stores with per-k16-group word permutation:
// word w -> g*8 + ((w&7)&3)*2 + ((w&7)>>2). A float4 (2 words, even w8) lands
// at permuted positions p0 and p0+2.
// ---------------------------------------------------------------------------
__device__ __forceinline__ void sts64h(uint32_t* __restrict__ dst, const float4 r[8],
                                       int tid)
{
#pragma unroll
    for (int rr = 0; rr < 2; rr++) {
        const int row = (tid >> 2) + rr * 64;
        uint32_t* d = dst + row * KS_W;
#pragma unroll
        for (int cc = 0; cc < 4; cc++) {
            const int c4 = ((tid & 3) + cc * 4) << 2;
            const int w = c4 >> 1, g = w >> 3, w8 = w & 7;
            const int p0 = (w8 & 3) * 2 + (w8 >> 2);
            const float4 v = r[rr * 4 + cc];
            d[g * 8 + p0]     = pack_h2(v.x, v.y);
            d[g * 8 + p0 + 2] = pack_h2(v.z, v.w);
        }
    }
}
__device__ __forceinline__ void stsvh(uint32_t* __restrict__ dst, const float4 r[8],
                                      int tid)
{
#pragma unroll
    for (int rr = 0; rr < 2; rr++) {
        const int dd = (tid >> 3) + rr * 32;
        uint32_t* dr = dst + dd * VS_W;
#pragma unroll
        for (int cc = 0; cc < 4; cc++) {
            const int c4 = ((tid & 7) + cc * 8) << 2;
            const int w = c4 >> 1, g = w >> 3, w8 = w & 7;
            const int p0 = (w8 & 3) * 2 + (w8 >> 2);
            const float4 v = r[rr * 4 + cc];
            dr[g * 8 + p0]     = pack_h2(v.x, v.y);
            dr[g * 8 + p0 + 2] = pack_h2(v.z, v.w);
        }
    }
}

// ===========================================================================
// Fused attention v3 (validated round 11): fp16 m16n8k16, zero shuffles.
// One block per (bh, q-tile of 128), 8 warps, each warp owns 16 q-rows.
// ===========================================================================
__global__ __launch_bounds__(256, 2)
void fused_attn()
{
    extern __shared__ uint32_t sm[];
    uint32_t* Ks = sm;                    // [128][KS_W]  (half2 words)
    uint32_t* Vs = sm + 128 * KS_W;       // [64][VS_W]

    const int qt = blockIdx.x, bh = blockIdx.y;
    const int tid = threadIdx.x, lane = tid & 31, warp = tid >> 5;
    const int gid = lane >> 2, tig = lane & 3;
    const int r0 = warp * 16 + gid;       // this lane's low row within tile

    // ---- stage Q once through Ks buffer (fp16), pull A-fragments ----
    uint32_t qa[4][4];                    // 4 k16 groups x {a0,a1,a2,a3}
    {
        float4 q[8];
        load64_regs(q, g_q + ((size_t)bh * TT + qt * 128) * HD, tid);
        sts64h(Ks, q, tid);
        __syncthreads();
#pragma unroll
        for (int g = 0; g < 4; g++) {
            uint2 lo = *reinterpret_cast<const uint2*>(Ks + r0 * KS_W + 8 * g + 2 * tig);
            uint2 hi = *reinterpret_cast<const uint2*>(Ks + (r0 + 8) * KS_W + 8 * g + 2 * tig);
            qa[g][0] = lo.x; qa[g][1] = hi.x; qa[g][2] = lo.y; qa[g][3] = hi.y;
        }
        __syncthreads();
    }

    float oacc[8][4];
#pragma unroll
    for (int j = 0; j < 8; j++)
#pragma unroll
        for (int c = 0; c < 4; c++) oacc[j][c] = 0.0f;
    float zr0 = 0.0f, zr1 = 0.0f;

    const float* Kbase = g_k + (size_t)bh * TT * HD;
    const float* Vbase = g_vt + (size_t)bh * HD * TT;
    __half* p16r0 = g_p16 + ((size_t)bh * TT + qt * 128 + r0) * TT;
    __half* p16r1 = p16r0 + (size_t)8 * TT;

#pragma unroll 1
    for (int kt = 0; kt < 16; kt++) {
        __syncthreads();   // prior iter's consumers done with Ks/Vs
        {
            float4 kr[8];
            load64_regs(kr, Kbase + (size_t)kt * 128 * HD, tid);
            sts64h(Ks, kr, tid);
        }
        {
            float4 vr[8];
            loadv_regs(vr, Vbase + kt * 128, tid);
            stsvh(Vs, vr, tid);
        }
        __syncthreads();

#pragma unroll 1
        for (int half = 0; half < 2; half++) {
            // ---- S half: rows [16w,16w+16), cols [64*half, 64*half+64) ----
            float acc[8][4];
#pragma unroll
            for (int jj = 0; jj < 8; jj++)
#pragma unroll
                for (int c = 0; c < 4; c++) acc[jj][c] = 0.0f;

#pragma unroll
            for (int g = 0; g < 4; g++) {
#pragma unroll
                for (int jj = 0; jj < 8; jj++) {
                    const int j = half * 8 + jj;
                    uint2 b = *reinterpret_cast<const uint2*>(
                        Ks + (8 * j + gid) * KS_W + 8 * g + 2 * tig);
                    MMA_F16(acc[jj], qa[g][0], qa[g][1], qa[g][2], qa[g][3],
                            b.x, b.y);
                }
            }

            // ---- exp, Z, fp16 pack (+side-store) ----
            uint32_t ph01[8], ph23[8];
#pragma unroll
            for (int jj = 0; jj < 8; jj++) {
                const float e0 = __expf(acc[jj][0]);
                const float e1 = __expf(acc[jj][1]);
                const float e2 = __expf(acc[jj][2]);
                const float e3 = __expf(acc[jj][3]);
                zr0 += e0 + e1;
                zr1 += e2 + e3;
                ph01[jj] = pack_h2(e0, e1);
                ph23[jj] = pack_h2(e2, e3);
                const int colk = kt * 128 + half * 64 + jj * 8 + 2 * tig;
                *reinterpret_cast<uint32_t*>(p16r0 + colk) = ph01[jj];
                *reinterpret_cast<uint32_t*>(p16r1 + colk) = ph23[jj];
            }

            // ---- O += P V : C-frag == A-frag, groups 4*half..4*half+3 ----
#pragma unroll
            for (int gp = 0; gp < 4; gp++) {
                const int g = half * 4 + gp;
                const uint32_t a0 = ph01[2 * gp],     a1 = ph23[2 * gp];
                const uint32_t a2 = ph01[2 * gp + 1], a3 = ph23[2 * gp + 1];
#pragma unroll
                for (int j2 = 0; j2 < 8; j2++) {
                    uint2 b = *reinterpret_cast<const uint2*>(
                        Vs + (8 * j2 + gid) * VS_W + 8 * g + 2 * tig);
                    MMA_F16(oacc[j2], a0, a1, a2, a3, b.x, b.y);
                }
            }
        }
    }

    // ---- Z: reduce over quad ----
    zr0 += __shfl_xor_sync(0xffffffffu, zr0, 1);
    zr0 += __shfl_xor_sync(0xffffffffu, zr0, 2);
    zr1 += __shfl_xor_sync(0xffffffffu, zr1, 1);
    zr1 += __shfl_xor_sync(0xffffffffu, zr1, 2);
    if (tig == 0) {
        g_Z[(size_t)bh * TT + qt * 128 + r0]     = zr0;
        g_Z[(size_t)bh * TT + qt * 128 + r0 + 8] = zr1;
    }

    // ---- epilogue: O / Z -> g_mid [t][b][e] ----
    const int b = bh >> 3, h = bh & 7;
    const float rz0 = 1.0f / zr0;
    const float rz1 = 1.0f / zr1;
#pragma unroll
    for (int j2 = 0; j2 < 8; j2++) {
        const int d = h * HD + j2 * 8 + 2 * tig;
        const int t0 = qt * 128 + r0;
        float2 v0 = make_float2(oacc[j2][0] * rz0, oacc[j2][1] * rz0);
        float2 v1 = make_float2(oacc[j2][2] * rz1, oacc[j2][3] * rz1);
        *reinterpret_cast<float2*>(&g_mid[((size_t)t0 * BB + b) * EE + d])       = v0;
        *reinterpret_cast<float2*>(&g_mid[((size_t)(t0 + 8) * BB + b) * EE + d]) = v1;
    }
}

// ===========================================================================
// avg pass (validated rounds 9-11): memory-bound scale-and-sum over fp16 expS.
// ===========================================================================
__global__ __launch_bounds__(256)
void avg_scale(float* __restrict__ avg_out)
{
    const int q = blockIdx.x, b = blockIdx.y;
    const int tid = threadIdx.x;
    const int k0 = tid * 8;

    float acc[8];
#pragma unroll
    for (int i = 0; i < 8; i++) acc[i] = 0.0f;

#pragma unroll
    for (int h = 0; h < HH; h++) {
        const int bh = b * HH + h;
        const float rz = 0.125f / g_Z[(size_t)bh * TT + q];
        const uint4 raw = *reinterpret_cast<const uint4*>(
            g_p16 + ((size_t)bh * TT + q) * TT + k0);
        const __half2* hp = reinterpret_cast<const __half2*>(&raw);
#pragma unroll
        for (int i = 0; i < 4; i++) {
            const float2 f = __half22float2(hp[i]);
            acc[2 * i]     += f.x * rz;
            acc[2 * i + 1] += f.y * rz;
        }
    }

    float* dst = avg_out + ((size_t)b * TT + q) * TT + k0;
    *reinterpret_cast<float4*>(dst)     = make_float4(acc[0], acc[1], acc[2], acc[3]);
    *reinterpret_cast<float4*>(dst + 4) = make_float4(acc[4], acc[5], acc[6], acc[7]);
}

// ===========================================================================
// fp16 GEMM for QKV in-projection (EPI 0) and out-projection (EPI 3).
// C = A * B^T (+bias), fp32 accumulate. BK=16 = one m16n8k16 group per iter.
// smem rows: 8 packed half2 words (stride 8): pair index = 4*(row%4)+tig ->
// conflict-free LDS.64 fragment loads. Double-buffered.
// ===========================================================================
template<int EPI, int BM, int BN, int WM, int WN, int K, int LDA, int LDB>
__global__ __launch_bounds__(256)
void mma_gemm(const float* __restrict__ Aext, const float* __restrict__ Bext,
              const float* __restrict__ bias, float* __restrict__ Cext)
{
    constexpr int BK = 16;
    constexpr int WARPS_N = BN / WN;
    constexpr int MT = WM / 16;
    constexpr int NT = WN / 8;
    static_assert((BM / WM) * (BN / WN) == 8, "8 warps");

    const int tid  = threadIdx.x;
    const int lane = tid & 31;
    const int warp = tid >> 5;
    const int wm0  = (warp / WARPS_N) * WM;
    const int wn0  = (warp % WARPS_N) * WN;
    const int m0   = blockIdx.y * BM;
    const int n0   = blockIdx.x * BN;

    const float* A  = (EPI == 0) ? Aext : g_mid;
    const float* Bm = Bext;

    __shared__ __align__(16) uint32_t As[2][BM][8];
    __shared__ __align__(16) uint32_t Bs[2][BN][8];

    float acc[MT][NT][4];
#pragma unroll
    for (int i = 0; i < MT; i++)
#pragma unroll
        for (int j = 0; j < NT; j++)
#pragma unroll
            for (int c = 0; c < 4; c++) acc[i][j][c] = 0.0f;

    const int lrow = tid >> 2;
    const int lcol = (tid & 3) << 2;              // float col 0,4,8,12
    const int w0   = lcol >> 1;                   // half2 word 0,2,4,6
    const int p0   = (w0 & 3) * 2 + (w0 >> 2);    // permuted word 0,4,1,5

    const int gid = lane >> 2;
    const int tig = lane & 3;

    // Prologue: stage k0=0 into buffer 0 (fp16 packed)
#pragma unroll
    for (int r = lrow; r < BM; r += 64) {
        float4 v = *reinterpret_cast<const float4*>(&A[(size_t)(m0 + r) * LDA + lcol]);
        As[0][r][p0]     = pack_h2(v.x, v.y);
        As[0][r][p0 + 2] = pack_h2(v.z, v.w);
    }
#pragma unroll
    for (int r = lrow; r < BN; r += 64) {
        float4 v = *reinterpret_cast<const float4*>(&Bm[(size_t)(n0 + r) * LDB + lcol]);
        Bs[0][r][p0]     = pack_h2(v.x, v.y);
        Bs[0][r][p0 + 2] = pack_h2(v.z, v.w);
    }
    __syncthreads();

    int buf = 0;

#pragma unroll 1
    for (int k0 = 0; k0 < K; k0 += BK) {
        const bool has_next = (k0 + BK) < K;
        float4 pa[BM / 64], pb[(BN + 63) / 64];
        if (has_next) {
#pragma unroll
            for (int q = 0; q < BM / 64; q++)
                pa[q] = *reinterpret_cast<const float4*>(
                    &A[(size_t)(m0 + lrow + q * 64) * LDA + k0 + BK + lcol]);
#pragma unroll
            for (int q = 0; q < (BN + 63) / 64; q++)
                if (lrow + q * 64 < BN)
                    pb[q] = *reinterpret_cast<const float4*>(
                        &Bm[(size_t)(n0 + lrow + q * 64) * LDB + k0 + BK + lcol]);
        }

        // Compute current buffer: one k16 group
        {
            uint2 alo[MT], ahi[MT], bfr[NT];
#pragma unroll
            for (int i = 0; i < MT; i++) {
                const int row = wm0 + i * 16 + gid;
                alo[i] = *reinterpret_cast<const uint2*>(&As[buf][row][2 * tig]);
                ahi[i] = *reinterpret_cast<const uint2*>(&As[buf][row + 8][2 * tig]);
            }
#pragma unroll
            for (int j = 0; j < NT; j++)
                bfr[j] = *reinterpret_cast<const uint2*>(&Bs[buf][wn0 + j * 8 + gid][2 * tig]);
#pragma unroll
            for (int i = 0; i < MT; i++)
#pragma unroll
                for (int j = 0; j < NT; j++)
                    MMA_F16(acc[i][j], alo[i].x, ahi[i].x, alo[i].y, ahi[i].y,
                            bfr[j].x, bfr[j].y);
        }

        if (has_next) {
            const int nb = buf ^ 1;
#pragma unroll
            for (int q = 0; q < BM / 64; q++) {
                const int r = lrow + q * 64;
                As[nb][r][p0]     = pack_h2(pa[q].x, pa[q].y);
                As[nb][r][p0 + 2] = pack_h2(pa[q].z, pa[q].w);
            }
#pragma unroll
            for (int q = 0; q < (BN + 63) / 64; q++) {
                const int r = lrow + q * 64;
                if (r < BN) {
                    Bs[nb][r][p0]     = pack_h2(pb[q].x, pb[q].y);
                    Bs[nb][r][p0 + 2] = pack_h2(pb[q].z, pb[q].w);
                }
            }
            __syncthreads();
            buf = nb;
        }
    }

    // Epilogue
#pragma unroll
    for (int i = 0; i < MT; i++) {
        const int rbase = m0 + wm0 + i * 16 + gid;
#pragma unroll
        for (int j = 0; j < NT; j++) {
            const int cbase = n0 + wn0 + j * 8 + tig * 2;
#pragma unroll
            for (int c = 0; c < 4; c++) {
                const int m = rbase + (c >> 1) * 8;
                const int n = cbase + (c & 1);
                float v = acc[i][j][c] + bias[n];
                if constexpr (EPI == 0) {
                    const int t = m >> 2, b = m & 3;
                    const int sec = n >> 9, h = (n >> 6) & 7, d = n & 63;
                    const int bh = b * HH + h;
                    if (sec == 0)
                        g_q[((size_t)bh * TT + t) * HD + d] = v * SCALE;
                    else if (sec == 1)
                        g_k[((size_t)bh * TT + t) * HD + d] = v;
                    else
                        g_vt[((size_t)bh * HD + d) * TT + t] = v;
                } else {
                    Cext[(size_t)m * EE + n] = v;
                }
            }
        }
    }
}

// ---------------------------------------------------------------------------
extern "C" void kernel_launch(void* const* d_in, const int* in_sizes, int n_in,
                              void* d_out, int out_size)
{
    const float* x     = (const float*)d_in[0];  // [T,B,E]
    const float* w_in  = (const float*)d_in[1];  // [3E,E]
    const float* b_in  = (const float*)d_in[2];  // [3E]
    const float* w_out = (const float*)d_in[3];  // [E,E]
    const float* b_out = (const float*)d_in[4];  // [E]

    float* out      = (float*)d_out;
    float* attn_out = out;                              // T*B*E
    float* avg_out  = out + (size_t)TT * BB * EE;       // B*T*T

    cudaFuncSetAttribute(fused_attn, cudaFuncAttributeMaxDynamicSharedMemorySize,
                         FUSED_SMEM);

    // 1) QKV in-projection: [8192,512] x [1536,512]^T  (fp16 mma)
    {
        dim3 grid(3 * EE / 128, (TT * BB) / 128, 1);
        mma_gemm<0, 128, 128, 64, 32, EE, EE, EE><<<grid, 256>>>(x, w_in, b_in, nullptr);
    }
    // 2) Fused attention (fp16 mma): scores + exp + rowsum + PV (+ fp16 expS)
    {
        dim3 grid(TT / 128, BH, 1);
        fused_attn<<<grid, 256, FUSED_SMEM>>>();
    }
    // 3) avg_weights: memory-bound scale-and-sum over fp16 expS
    {
        dim3 grid(TT, BB, 1);
        avg_scale<<<grid, 256>>>(avg_out);
    }
    // 4) Out projection: [8192,512] x [512,512]^T -> d_out  (fp16 mma)
    {
        dim3 grid(EE / 128, (TT * BB) / 128, 1);
        mma_gemm<3, 128, 128, 64, 32, EE, EE, EE><<<grid, 256>>>(nullptr, w_out, b_out, attn_out);
    }
}